// round 9
// baseline (speedup 1.0000x reference)
#include <cuda_runtime.h>
#include <cuda_fp16.h>
#include <cstdint>

// Problem constants
#define VOCAB 32000
#define DMODEL 1024
#define NHEAD 16
#define HDIM 64
#define FFDIM 4096
#define NLAYER 4
#define SEQ 2048
#define BATCH 2
#define MTOK (BATCH * SEQ)      // 4096 token rows
#define HK (NHEAD * HDIM)       // 1024
#define QKVN 3072               // fused q|k|v output width

// ---------------------------------------------------------------------------
// Scratch (device globals; no allocations allowed)
// ---------------------------------------------------------------------------
__device__ float g_x[MTOK * DMODEL];                 // residual stream fp32
__device__ float g_qkv[MTOK * QKVN];                 // fused qkv fp32
__device__ float g_qkvb[NLAYER * QKVN];              // fused qkv bias
__device__ __half g_xh[MTOK * DMODEL];               // activations fp16
__device__ __half g_ah[MTOK * HK];
__device__ __half g_fh[MTOK * FFDIM];
// fp16 weights, NATURAL [K,N] layout
__device__ __half g_wqkv[NLAYER * DMODEL * QKVN];
__device__ __half g_wo[NLAYER * HK * DMODEL];
__device__ __half g_w1[NLAYER * DMODEL * FFDIM];
__device__ __half g_w2[NLAYER * FFDIM * DMODEL];
__device__ __half g_wf[DMODEL * VOCAB];

// ---------------------------------------------------------------------------
// PTX helpers (all sm_80-era, arch-portable)
// ---------------------------------------------------------------------------
__device__ __forceinline__ uint32_t smem_u32(const void* p) {
    return (uint32_t)__cvta_generic_to_shared(p);
}
__device__ __forceinline__ void cp_async16(uint32_t dst, const void* src) {
    asm volatile("cp.async.cg.shared.global [%0], [%1], 16;\n" :: "r"(dst), "l"(src));
}
__device__ __forceinline__ void cp_commit() { asm volatile("cp.async.commit_group;\n" ::: "memory"); }
template<int N> __device__ __forceinline__ void cp_wait() {
    asm volatile("cp.async.wait_group %0;\n" :: "n"(N) : "memory");
}
__device__ __forceinline__ void ldsm_x4(uint32_t* r, uint32_t addr) {
    asm volatile("ldmatrix.sync.aligned.m8n8.x4.shared.b16 {%0,%1,%2,%3}, [%4];"
                 : "=r"(r[0]), "=r"(r[1]), "=r"(r[2]), "=r"(r[3]) : "r"(addr));
}
__device__ __forceinline__ void ldsm_x4_trans(uint32_t* r, uint32_t addr) {
    asm volatile("ldmatrix.sync.aligned.m8n8.x4.trans.shared.b16 {%0,%1,%2,%3}, [%4];"
                 : "=r"(r[0]), "=r"(r[1]), "=r"(r[2]), "=r"(r[3]) : "r"(addr));
}
__device__ __forceinline__ void mma_f16(float* c, const uint32_t* a, const uint32_t* b) {
    asm volatile(
        "mma.sync.aligned.m16n8k16.row.col.f32.f16.f16.f32 "
        "{%0,%1,%2,%3}, {%4,%5,%6,%7}, {%8,%9}, {%0,%1,%2,%3};"
        : "+f"(c[0]), "+f"(c[1]), "+f"(c[2]), "+f"(c[3])
        : "r"(a[0]), "r"(a[1]), "r"(a[2]), "r"(a[3]), "r"(b[0]), "r"(b[1]));
}

// ---------------------------------------------------------------------------
// Weight convert (NO transpose): W [K,N] fp32 -> fp16 [K,N], optional col pack.
// ---------------------------------------------------------------------------
__global__ void wsplit_kernel(const float* __restrict__ W,
                              __half* __restrict__ Wh,
                              int ncols4, int ostride4, int coff4)
{
    int row = blockIdx.x;
    int c4 = blockIdx.y * blockDim.x + threadIdx.x;
    if (c4 >= ncols4) return;
    float4 v = *(const float4*)(W + ((long)row * ncols4 + c4) * 4);
    __half2 h01, h23;
    h01.x = __float2half_rn(v.x); h01.y = __float2half_rn(v.y);
    h23.x = __float2half_rn(v.z); h23.y = __float2half_rn(v.w);
    __half2* ph = (__half2*)(Wh + ((long)row * ostride4 + coff4 + c4) * 4);
    ph[0] = h01; ph[1] = h23;
}

// ---------------------------------------------------------------------------
// Embedding: x = emb[token] + pos ; also writes fp16
// ---------------------------------------------------------------------------
__global__ void embed_kernel(const int* __restrict__ tokens,
                             const float* __restrict__ emb,
                             const float* __restrict__ pos,
                             float* __restrict__ x,
                             __half* __restrict__ xh)
{
    int row = blockIdx.x;
    int s = row & (SEQ - 1);
    int t = tokens[row];
    const float4* e = (const float4*)(emb + (long)t * DMODEL);
    const float4* p = (const float4*)(pos + (long)s * DMODEL);
    for (int d = threadIdx.x; d < DMODEL / 4; d += blockDim.x) {
        float4 a = e[d], b = p[d];
        a.x += b.x; a.y += b.y; a.z += b.z; a.w += b.w;
        long o = (long)row * DMODEL + d * 4;
        *(float4*)&x[o] = a;
        __half2 h01, h23;
        h01.x = __float2half_rn(a.x); h01.y = __float2half_rn(a.y);
        h23.x = __float2half_rn(a.z); h23.y = __float2half_rn(a.w);
        *(__half2*)&xh[o] = h01; *(__half2*)&xh[o + 2] = h23;
    }
}

// qkv bias concat
__global__ void bias_concat_kernel(const float* __restrict__ bq, const float* __restrict__ bk,
                                   const float* __restrict__ bv, float* __restrict__ out)
{
    int i = blockIdx.x * blockDim.x + threadIdx.x;
    if (i >= NLAYER * QKVN) return;
    int l = i / QKVN, c = i - l * QKVN;
    float v = (c < 1024) ? bq[l * 1024 + c]
            : (c < 2048) ? bk[l * 1024 + c - 1024]
                         : bv[l * 1024 + c - 2048];
    out[i] = v;
}

// ---------------------------------------------------------------------------
// Narrow HMMA GEMM (128x128 CTA, warp tile 64x32, 2 CTAs/SM) — for N=1024
// ---------------------------------------------------------------------------
#define ASTRIDE 80                  // A smem row stride bytes (32 halves + pad)
#define ATILE_B 10240               // [128][40] halves
#define BSTRIDE 272                 // B smem row stride bytes (128 halves + pad)
#define BTILE_B 8704                // [32][136] halves
#define STAGE_B (ATILE_B + BTILE_B)       // 18944
#define GEMM_SMEM (4 * STAGE_B)           // 75776

template<bool RELU, bool RESID, bool WF32, bool WH16>
__global__ __launch_bounds__(256, 2)
void hmma_gemm(const __half* __restrict__ A, const __half* __restrict__ B,
               const float* __restrict__ bias, const float* __restrict__ resid,
               float* __restrict__ Cf, __half* __restrict__ Ch,
               int N, int K)
{
    extern __shared__ char smem[];
    uint32_t sbase = smem_u32(smem);

    int tid = threadIdx.x;
    int lane = tid & 31;
    int wid = tid >> 5;
    int wm = wid & 1;
    int wn = wid >> 1;
    int row0 = blockIdx.x * 128;
    int ncol0 = blockIdx.y * 128;
    int nk = K >> 5;

    float c[4][4][4];
#pragma unroll
    for (int i = 0; i < 4; i++)
#pragma unroll
        for (int j = 0; j < 4; j++)
#pragma unroll
            for (int k = 0; k < 4; k++) c[i][j][k] = 0.f;

    auto load_stage = [&](int chunk, int buf) {
        uint32_t sb = sbase + buf * STAGE_B;
        int kc = chunk << 5;
#pragma unroll 2
        for (int i = tid; i < 512; i += 256) {
            int r = i >> 2, cc = i & 3;
            cp_async16(sb + (uint32_t)(r * ASTRIDE + cc * 16),
                       A + (long)(row0 + r) * K + kc + cc * 8);
        }
#pragma unroll 2
        for (int i = tid; i < 512; i += 256) {
            int r = i >> 4, cc = i & 15;
            cp_async16(sb + ATILE_B + (uint32_t)(r * BSTRIDE + cc * 16),
                       B + (long)(kc + r) * N + ncol0 + cc * 8);
        }
        cp_commit();
    };

    load_stage(0, 0);
    load_stage(1, 1);
    load_stage(2, 2);

    int arow = (lane & 7) + ((lane >> 3) & 1) * 8;
    int akk = ((lane >> 4) & 1) * 8;
    int bt = lane >> 3, br = lane & 7;
    int brow_off = (bt & 1) * 8 + br;
    int bcol_off = (bt >> 1) * 8;

    for (int ch = 0; ch < nk; ch++) {
        int buf = ch & 3;
        if (ch + 2 < nk)      cp_wait<2>();
        else if (ch + 1 < nk) cp_wait<1>();
        else                  cp_wait<0>();
        __syncthreads();
        if (ch + 3 < nk) load_stage(ch + 3, (ch + 3) & 3);

        uint32_t sb = sbase + buf * STAGE_B;
#pragma unroll
        for (int ks = 0; ks < 2; ks++) {
            int k0 = ks * 16;
            uint32_t a_r[4][4], b_r[4][2];
#pragma unroll
            for (int mi = 0; mi < 4; mi++) {
                uint32_t ad = sb + (uint32_t)((wm * 64 + mi * 16 + arow) * ASTRIDE
                                              + (k0 + akk) * 2);
                ldsm_x4(a_r[mi], ad);
            }
#pragma unroll
            for (int p = 0; p < 2; p++) {
                uint32_t bd = sb + ATILE_B
                            + (uint32_t)((k0 + brow_off) * BSTRIDE
                                         + (wn * 32 + p * 16 + bcol_off) * 2);
                uint32_t r[4];
                ldsm_x4_trans(r, bd);
                b_r[2 * p][0] = r[0]; b_r[2 * p][1] = r[1];
                b_r[2 * p + 1][0] = r[2]; b_r[2 * p + 1][1] = r[3];
            }
#pragma unroll
            for (int mi = 0; mi < 4; mi++)
#pragma unroll
                for (int ni = 0; ni < 4; ni++)
                    mma_f16(c[mi][ni], a_r[mi], b_r[ni]);
        }
    }

    int rbase = row0 + wm * 64 + (lane >> 2);
    int cbase = ncol0 + wn * 32 + (lane & 3) * 2;
#pragma unroll
    for (int mi = 0; mi < 4; mi++) {
#pragma unroll
        for (int ni = 0; ni < 4; ni++) {
            int gc = cbase + ni * 8;
            float b0 = __ldg(&bias[gc]), b1 = __ldg(&bias[gc + 1]);
#pragma unroll
            for (int half_ = 0; half_ < 2; half_++) {
                long gr = rbase + mi * 16 + half_ * 8;
                float v0 = c[mi][ni][half_ * 2 + 0] + b0;
                float v1 = c[mi][ni][half_ * 2 + 1] + b1;
                if (RELU) { v0 = fmaxf(v0, 0.f); v1 = fmaxf(v1, 0.f); }
                if (RESID) {
                    float2 rr = *(const float2*)&resid[gr * N + gc];
                    v0 += rr.x; v1 += rr.y;
                }
                if (WF32) {
                    float2 o; o.x = v0; o.y = v1;
                    *(float2*)&Cf[gr * N + gc] = o;
                }
                if (WH16) {
                    __half2 hh;
                    hh.x = __float2half_rn(v0); hh.y = __float2half_rn(v1);
                    *(__half2*)&Ch[gr * N + gc] = hh;
                }
            }
        }
    }
}

// ---------------------------------------------------------------------------
// Wide HMMA GEMM (128x256 CTA, warp tile 64x64, 1 CTA/SM) — for N>=3072
// Higher HMMA issue fraction: per ks, 8 ldsm feed 32 mma.
// ---------------------------------------------------------------------------
#define WBSTRIDE 528                // B smem row stride bytes (256 halves + pad)
#define WBTILE_B 16896              // [32][264] halves
#define WSTAGE_B (ATILE_B + WBTILE_B)     // 27136
#define WGEMM_SMEM (4 * WSTAGE_B)         // 108544

template<bool RELU, bool WF32, bool WH16>
__global__ __launch_bounds__(256, 1)
void hmma_gemm_wide(const __half* __restrict__ A, const __half* __restrict__ B,
                    const float* __restrict__ bias,
                    float* __restrict__ Cf, __half* __restrict__ Ch,
                    int N, int K)
{
    extern __shared__ char smem[];
    uint32_t sbase = smem_u32(smem);

    int tid = threadIdx.x;
    int lane = tid & 31;
    int wid = tid >> 5;
    int wm = wid & 1;          // 2 warps over M (64 rows)
    int wn = wid >> 1;         // 4 warps over N (64 cols each)
    int row0 = blockIdx.x * 128;
    int ncol0 = blockIdx.y * 256;
    int nk = K >> 5;

    float c[4][8][4];
#pragma unroll
    for (int i = 0; i < 4; i++)
#pragma unroll
        for (int j = 0; j < 8; j++)
#pragma unroll
            for (int k = 0; k < 4; k++) c[i][j][k] = 0.f;

    auto load_stage = [&](int chunk, int buf) {
        uint32_t sb = sbase + buf * WSTAGE_B;
        int kc = chunk << 5;
        // A: 128 rows x 64B (512 cp)
#pragma unroll 2
        for (int i = tid; i < 512; i += 256) {
            int r = i >> 2, cc = i & 3;
            cp_async16(sb + (uint32_t)(r * ASTRIDE + cc * 16),
                       A + (long)(row0 + r) * K + kc + cc * 8);
        }
        // B: 32 rows x 512B (1024 cp)
#pragma unroll 4
        for (int i = tid; i < 1024; i += 256) {
            int r = i >> 5, cc = i & 31;
            cp_async16(sb + ATILE_B + (uint32_t)(r * WBSTRIDE + cc * 16),
                       B + (long)(kc + r) * N + ncol0 + cc * 8);
        }
        cp_commit();
    };

    load_stage(0, 0);
    load_stage(1, 1);
    load_stage(2, 2);

    int arow = (lane & 7) + ((lane >> 3) & 1) * 8;
    int akk = ((lane >> 4) & 1) * 8;
    int bt = lane >> 3, br = lane & 7;
    int brow_off = (bt & 1) * 8 + br;
    int bcol_off = (bt >> 1) * 8;

    for (int ch = 0; ch < nk; ch++) {
        int buf = ch & 3;
        if (ch + 2 < nk)      cp_wait<2>();
        else if (ch + 1 < nk) cp_wait<1>();
        else                  cp_wait<0>();
        __syncthreads();
        if (ch + 3 < nk) load_stage(ch + 3, (ch + 3) & 3);

        uint32_t sb = sbase + buf * WSTAGE_B;
#pragma unroll
        for (int ks = 0; ks < 2; ks++) {
            int k0 = ks * 16;
            uint32_t a_r[4][4], b_r[8][2];
#pragma unroll
            for (int mi = 0; mi < 4; mi++) {
                uint32_t ad = sb + (uint32_t)((wm * 64 + mi * 16 + arow) * ASTRIDE
                                              + (k0 + akk) * 2);
                ldsm_x4(a_r[mi], ad);
            }
#pragma unroll
            for (int p = 0; p < 4; p++) {
                uint32_t bd = sb + ATILE_B
                            + (uint32_t)((k0 + brow_off) * WBSTRIDE
                                         + (wn * 64 + p * 16 + bcol_off) * 2);
                uint32_t r[4];
                ldsm_x4_trans(r, bd);
                b_r[2 * p][0] = r[0]; b_r[2 * p][1] = r[1];
                b_r[2 * p + 1][0] = r[2]; b_r[2 * p + 1][1] = r[3];
            }
#pragma unroll
            for (int mi = 0; mi < 4; mi++)
#pragma unroll
                for (int ni = 0; ni < 8; ni++)
                    mma_f16(c[mi][ni], a_r[mi], b_r[ni]);
        }
    }

    int rbase = row0 + wm * 64 + (lane >> 2);
    int cbase = ncol0 + wn * 64 + (lane & 3) * 2;
#pragma unroll
    for (int mi = 0; mi < 4; mi++) {
#pragma unroll
        for (int ni = 0; ni < 8; ni++) {
            int gc = cbase + ni * 8;
            float b0 = __ldg(&bias[gc]), b1 = __ldg(&bias[gc + 1]);
#pragma unroll
            for (int half_ = 0; half_ < 2; half_++) {
                long gr = rbase + mi * 16 + half_ * 8;
                float v0 = c[mi][ni][half_ * 2 + 0] + b0;
                float v1 = c[mi][ni][half_ * 2 + 1] + b1;
                if (RELU) { v0 = fmaxf(v0, 0.f); v1 = fmaxf(v1, 0.f); }
                if (WF32) {
                    float2 o; o.x = v0; o.y = v1;
                    *(float2*)&Cf[gr * N + gc] = o;
                }
                if (WH16) {
                    __half2 hh;
                    hh.x = __float2half_rn(v0); hh.y = __float2half_rn(v1);
                    *(__half2*)&Ch[gr * N + gc] = hh;
                }
            }
        }
    }
}

// ---------------------------------------------------------------------------
// Flash attention (fp32), reads fused qkv [M,3072], writes fp16 attn out
// ---------------------------------------------------------------------------
#define FPAD 68

__global__ __launch_bounds__(256)
void flash_attn_kernel(const float* __restrict__ QKV,
                       __half* __restrict__ Ao)
{
    extern __shared__ float sm[];
    float* Qs = sm;
    float* Ks = sm + 64 * FPAD;
    float* Vs = sm + 2 * 64 * FPAD;
    float* Ps = sm + 3 * 64 * FPAD;

    int qt = gridDim.x - 1 - blockIdx.x;
    int bh = blockIdx.y;
    int b = bh >> 4;
    int h = bh & 15;
    int tid = threadIdx.x;
    int tx = tid & 15;
    int ty = tid >> 4;

    long baseq = (long)b * SEQ * QKVN + h * HDIM;
    long basek = baseq + 1024;
    long basev = baseq + 2048;

    for (int i = tid; i < 64 * 16; i += 256) {
        int r = i >> 4, c4 = (i & 15) * 4;
        *(float4*)&Qs[r * FPAD + c4] =
            *(const float4*)&QKV[baseq + (long)(qt * 64 + r) * QKVN + c4];
    }

    float m[4], l[4], o[4][4];
#pragma unroll
    for (int i = 0; i < 4; i++) {
        m[i] = -1e30f; l[i] = 0.f;
#pragma unroll
        for (int j = 0; j < 4; j++) o[i][j] = 0.f;
    }

    for (int jt = 0; jt <= qt; jt++) {
        for (int i = tid; i < 64 * 16; i += 256) {
            int r = i >> 4, c4 = (i & 15) * 4;
            long off = (long)(jt * 64 + r) * QKVN + c4;
            *(float4*)&Ks[r * FPAD + c4] = *(const float4*)&QKV[basek + off];
            *(float4*)&Vs[r * FPAD + c4] = *(const float4*)&QKV[basev + off];
        }
        __syncthreads();

        float s[4][4];
#pragma unroll
        for (int i = 0; i < 4; i++)
#pragma unroll
            for (int j = 0; j < 4; j++) s[i][j] = 0.f;

#pragma unroll 4
        for (int k4 = 0; k4 < HDIM; k4 += 4) {
            float4 qv[4], kv[4];
#pragma unroll
            for (int i = 0; i < 4; i++)
                qv[i] = *(const float4*)&Qs[(ty * 4 + i) * FPAD + k4];
#pragma unroll
            for (int j = 0; j < 4; j++)
                kv[j] = *(const float4*)&Ks[(tx + 16 * j) * FPAD + k4];
#pragma unroll
            for (int i = 0; i < 4; i++)
#pragma unroll
                for (int j = 0; j < 4; j++) {
                    s[i][j] = fmaf(qv[i].x, kv[j].x, s[i][j]);
                    s[i][j] = fmaf(qv[i].y, kv[j].y, s[i][j]);
                    s[i][j] = fmaf(qv[i].z, kv[j].z, s[i][j]);
                    s[i][j] = fmaf(qv[i].w, kv[j].w, s[i][j]);
                }
        }

        if (jt == qt) {
#pragma unroll
            for (int i = 0; i < 4; i++) {
                int qloc = ty * 4 + i;
#pragma unroll
                for (int j = 0; j < 4; j++) {
                    int kloc = tx + 16 * j;
                    s[i][j] = (kloc > qloc) ? -1e30f : s[i][j] * 0.125f;
                }
            }
        } else {
#pragma unroll
            for (int i = 0; i < 4; i++)
#pragma unroll
                for (int j = 0; j < 4; j++) s[i][j] *= 0.125f;
        }

#pragma unroll
        for (int i = 0; i < 4; i++) {
            float rmax = fmaxf(fmaxf(s[i][0], s[i][1]), fmaxf(s[i][2], s[i][3]));
#pragma unroll
            for (int w = 1; w < 16; w <<= 1)
                rmax = fmaxf(rmax, __shfl_xor_sync(0xffffffffu, rmax, w));
            float mn = fmaxf(m[i], rmax);
            float corr = __expf(m[i] - mn);
            float rsum = 0.f;
#pragma unroll
            for (int j = 0; j < 4; j++) {
                float p = __expf(s[i][j] - mn);
                s[i][j] = p;
                rsum += p;
            }
#pragma unroll
            for (int w = 1; w < 16; w <<= 1)
                rsum += __shfl_xor_sync(0xffffffffu, rsum, w);
            l[i] = l[i] * corr + rsum;
            m[i] = mn;
#pragma unroll
            for (int j = 0; j < 4; j++) o[i][j] *= corr;
        }

#pragma unroll
        for (int i = 0; i < 4; i++)
#pragma unroll
            for (int j = 0; j < 4; j++)
                Ps[(ty * 4 + i) * FPAD + tx + 16 * j] = s[i][j];
        __syncthreads();

#pragma unroll 4
        for (int k4 = 0; k4 < 64; k4 += 4) {
            float4 pv[4];
#pragma unroll
            for (int i = 0; i < 4; i++)
                pv[i] = *(const float4*)&Ps[(ty * 4 + i) * FPAD + k4];
#pragma unroll
            for (int cc = 0; cc < 4; cc++) {
                float4 vv = *(const float4*)&Vs[(k4 + cc) * FPAD + tx * 4];
#pragma unroll
                for (int i = 0; i < 4; i++) {
                    float p = (cc == 0) ? pv[i].x : (cc == 1) ? pv[i].y
                              : (cc == 2) ? pv[i].z : pv[i].w;
                    o[i][0] = fmaf(p, vv.x, o[i][0]);
                    o[i][1] = fmaf(p, vv.y, o[i][1]);
                    o[i][2] = fmaf(p, vv.z, o[i][2]);
                    o[i][3] = fmaf(p, vv.w, o[i][3]);
                }
            }
        }
        __syncthreads();
    }

#pragma unroll
    for (int i = 0; i < 4; i++) {
        float inv = 1.0f / l[i];
        int qg = qt * 64 + ty * 4 + i;
        __half2 h01, h23;
        h01.x = __float2half_rn(o[i][0] * inv);
        h01.y = __float2half_rn(o[i][1] * inv);
        h23.x = __float2half_rn(o[i][2] * inv);
        h23.y = __float2half_rn(o[i][3] * inv);
        long oaddr = (long)(b * SEQ + qg) * HK + h * HDIM + tx * 4;
        *(__half2*)&Ao[oaddr] = h01; *(__half2*)&Ao[oaddr + 2] = h23;
    }
}

#define FLASH_SMEM (4 * 64 * FPAD * 4)

// ---------------------------------------------------------------------------
// Launch
// ---------------------------------------------------------------------------
extern "C" void kernel_launch(void* const* d_in, const int* in_sizes, int n_in,
                              void* d_out, int out_size)
{
    const int*   tokens = (const int*)  d_in[0];
    const float* emb    = (const float*)d_in[1];
    const float* pos    = (const float*)d_in[2];
    const float* Wq     = (const float*)d_in[3];
    const float* bq     = (const float*)d_in[4];
    const float* Wk     = (const float*)d_in[5];
    const float* bk     = (const float*)d_in[6];
    const float* Wv     = (const float*)d_in[7];
    const float* bv     = (const float*)d_in[8];
    const float* Wo     = (const float*)d_in[9];
    const float* bo     = (const float*)d_in[10];
    const float* W1     = (const float*)d_in[11];
    const float* b1     = (const float*)d_in[12];
    const float* W2     = (const float*)d_in[13];
    const float* b2     = (const float*)d_in[14];
    const float* Wf     = (const float*)d_in[15];
    const float* bf     = (const float*)d_in[16];
    float* out = (float*)d_out;

    float *x, *qkv, *qkvb;
    __half *xh, *ah, *fh;
    __half *wqkv, *wo, *w1, *w2, *wf;
    cudaGetSymbolAddress((void**)&x, g_x);
    cudaGetSymbolAddress((void**)&qkv, g_qkv);
    cudaGetSymbolAddress((void**)&qkvb, g_qkvb);
    cudaGetSymbolAddress((void**)&xh, g_xh);
    cudaGetSymbolAddress((void**)&ah, g_ah);
    cudaGetSymbolAddress((void**)&fh, g_fh);
    cudaGetSymbolAddress((void**)&wqkv, g_wqkv);
    cudaGetSymbolAddress((void**)&wo, g_wo);
    cudaGetSymbolAddress((void**)&w1, g_w1);
    cudaGetSymbolAddress((void**)&w2, g_w2);
    cudaGetSymbolAddress((void**)&wf, g_wf);

    static bool attr_set = false;
    if (!attr_set) {
        cudaFuncSetAttribute(flash_attn_kernel,
                             cudaFuncAttributeMaxDynamicSharedMemorySize, FLASH_SMEM);
        cudaFuncSetAttribute(hmma_gemm<false, true, true, true>,
                             cudaFuncAttributeMaxDynamicSharedMemorySize, GEMM_SMEM);
        cudaFuncSetAttribute(hmma_gemm_wide<false, true, false>,
                             cudaFuncAttributeMaxDynamicSharedMemorySize, WGEMM_SMEM);
        cudaFuncSetAttribute(hmma_gemm_wide<true, false, true>,
                             cudaFuncAttributeMaxDynamicSharedMemorySize, WGEMM_SMEM);
        attr_set = true;
    }

    // ---- weight convert (no transpose; [K,N] natural layout) ----
    for (int l = 0; l < NLAYER; l++) {
        wsplit_kernel<<<dim3(DMODEL, 1), 256>>>(Wq + (long)l * DMODEL * HK,
            wqkv + (long)l * DMODEL * QKVN, HK / 4, QKVN / 4, 0);
        wsplit_kernel<<<dim3(DMODEL, 1), 256>>>(Wk + (long)l * DMODEL * HK,
            wqkv + (long)l * DMODEL * QKVN, HK / 4, QKVN / 4, 1024 / 4);
        wsplit_kernel<<<dim3(DMODEL, 1), 256>>>(Wv + (long)l * DMODEL * HK,
            wqkv + (long)l * DMODEL * QKVN, HK / 4, QKVN / 4, 2048 / 4);
        wsplit_kernel<<<dim3(HK, 1), 256>>>(Wo + (long)l * HK * DMODEL,
            wo + (long)l * HK * DMODEL, DMODEL / 4, DMODEL / 4, 0);
        wsplit_kernel<<<dim3(DMODEL, 4), 256>>>(W1 + (long)l * DMODEL * FFDIM,
            w1 + (long)l * DMODEL * FFDIM, FFDIM / 4, FFDIM / 4, 0);
        wsplit_kernel<<<dim3(FFDIM, 1), 256>>>(W2 + (long)l * FFDIM * DMODEL,
            w2 + (long)l * FFDIM * DMODEL, DMODEL / 4, DMODEL / 4, 0);
    }
    wsplit_kernel<<<dim3(DMODEL, 32), 256>>>(Wf, wf, VOCAB / 4, VOCAB / 4, 0);
    bias_concat_kernel<<<(NLAYER * QKVN + 255) / 256, 256>>>(bq, bk, bv, qkvb);

    // ---- forward ----
    embed_kernel<<<MTOK, 256>>>(tokens, emb, pos, x, xh);

    dim3 gQKV(MTOK / 128, QKVN / 256);      // wide: 32 x 12
    dim3 gProj(MTOK / 128, DMODEL / 128);   // narrow: 32 x 8
    dim3 gFF1(MTOK / 128, FFDIM / 256);     // wide: 32 x 16
    dim3 gLogits(MTOK / 128, VOCAB / 256);  // wide: 32 x 125
    dim3 gAttn(SEQ / 64, BATCH * NHEAD);

    for (int l = 0; l < NLAYER; l++) {
        // qkv = x @ Wqkv + b  (fp32 out)
        hmma_gemm_wide<false, true, false><<<gQKV, 256, WGEMM_SMEM>>>(
            xh, wqkv + (long)l * DMODEL * QKVN, qkvb + (long)l * QKVN,
            qkv, nullptr, QKVN, DMODEL);

        flash_attn_kernel<<<gAttn, 256, FLASH_SMEM>>>(qkv, ah);

        // x = x + a @ Wo + bo  (fp32 + fp16 out)
        hmma_gemm<false, true, true, true><<<gProj, 256, GEMM_SMEM>>>(
            ah, wo + (long)l * HK * DMODEL,
            bo + (long)l * DMODEL, x, x, xh, DMODEL, HK);

        // f = relu(x @ W1 + b1)  (fp16 only)
        hmma_gemm_wide<true, false, true><<<gFF1, 256, WGEMM_SMEM>>>(
            xh, w1 + (long)l * DMODEL * FFDIM,
            b1 + (long)l * FFDIM, nullptr, fh, FFDIM, DMODEL);

        // x = x + f @ W2 + b2
        hmma_gemm<false, true, true, true><<<gProj, 256, GEMM_SMEM>>>(
            fh, w2 + (long)l * FFDIM * DMODEL,
            b2 + (long)l * DMODEL, x, x, xh, DMODEL, FFDIM);
    }

    // logits = x @ Wf + bf
    hmma_gemm_wide<false, true, false><<<gLogits, 256, WGEMM_SMEM>>>(
        xh, wf, bf, out, nullptr, VOCAB, DMODEL);
}

// round 10
// speedup vs baseline: 1.0885x; 1.0885x over previous
#include <cuda_runtime.h>
#include <cuda_fp16.h>
#include <cstdint>

// Problem constants
#define VOCAB 32000
#define DMODEL 1024
#define NHEAD 16
#define HDIM 64
#define FFDIM 4096
#define NLAYER 4
#define SEQ 2048
#define BATCH 2
#define MTOK (BATCH * SEQ)      // 4096 token rows
#define HK (NHEAD * HDIM)       // 1024
#define QKVN 3072               // fused q|k|v output width

// ---------------------------------------------------------------------------
// Scratch (device globals; no allocations allowed)
// ---------------------------------------------------------------------------
__device__ float g_x[MTOK * DMODEL];                 // residual stream fp32
__device__ float g_qkv[MTOK * QKVN];                 // fused qkv fp32
__device__ float g_qkvb[NLAYER * QKVN];              // fused qkv bias
__device__ __half g_xh[MTOK * DMODEL];               // activations fp16
__device__ __half g_ah[MTOK * HK];
__device__ __half g_fh[MTOK * FFDIM];
// fp16 weights, NATURAL [K,N] layout
__device__ __half g_wqkv[NLAYER * DMODEL * QKVN];
__device__ __half g_wo[NLAYER * HK * DMODEL];
__device__ __half g_w1[NLAYER * DMODEL * FFDIM];
__device__ __half g_w2[NLAYER * FFDIM * DMODEL];
__device__ __half g_wf[DMODEL * VOCAB];

// ---------------------------------------------------------------------------
// PTX helpers (all sm_80-era, arch-portable)
// ---------------------------------------------------------------------------
__device__ __forceinline__ uint32_t smem_u32(const void* p) {
    return (uint32_t)__cvta_generic_to_shared(p);
}
__device__ __forceinline__ void cp_async16(uint32_t dst, const void* src) {
    asm volatile("cp.async.cg.shared.global [%0], [%1], 16;\n" :: "r"(dst), "l"(src));
}
__device__ __forceinline__ void cp_commit() { asm volatile("cp.async.commit_group;\n" ::: "memory"); }
template<int N> __device__ __forceinline__ void cp_wait() {
    asm volatile("cp.async.wait_group %0;\n" :: "n"(N) : "memory");
}
__device__ __forceinline__ void ldsm_x4(uint32_t* r, uint32_t addr) {
    asm volatile("ldmatrix.sync.aligned.m8n8.x4.shared.b16 {%0,%1,%2,%3}, [%4];"
                 : "=r"(r[0]), "=r"(r[1]), "=r"(r[2]), "=r"(r[3]) : "r"(addr));
}
__device__ __forceinline__ void ldsm_x4_trans(uint32_t* r, uint32_t addr) {
    asm volatile("ldmatrix.sync.aligned.m8n8.x4.trans.shared.b16 {%0,%1,%2,%3}, [%4];"
                 : "=r"(r[0]), "=r"(r[1]), "=r"(r[2]), "=r"(r[3]) : "r"(addr));
}
__device__ __forceinline__ void mma_f16(float* c, const uint32_t* a, const uint32_t* b) {
    asm volatile(
        "mma.sync.aligned.m16n8k16.row.col.f32.f16.f16.f32 "
        "{%0,%1,%2,%3}, {%4,%5,%6,%7}, {%8,%9}, {%0,%1,%2,%3};"
        : "+f"(c[0]), "+f"(c[1]), "+f"(c[2]), "+f"(c[3])
        : "r"(a[0]), "r"(a[1]), "r"(a[2]), "r"(a[3]), "r"(b[0]), "r"(b[1]));
}

// ---------------------------------------------------------------------------
// Weight convert (NO transpose): W [K,N] fp32 -> fp16 [K,N], optional col pack.
// ---------------------------------------------------------------------------
__global__ void wsplit_kernel(const float* __restrict__ W,
                              __half* __restrict__ Wh,
                              int ncols4, int ostride4, int coff4)
{
    int row = blockIdx.x;
    int c4 = blockIdx.y * blockDim.x + threadIdx.x;
    if (c4 >= ncols4) return;
    float4 v = *(const float4*)(W + ((long)row * ncols4 + c4) * 4);
    __half2 h01, h23;
    h01.x = __float2half_rn(v.x); h01.y = __float2half_rn(v.y);
    h23.x = __float2half_rn(v.z); h23.y = __float2half_rn(v.w);
    __half2* ph = (__half2*)(Wh + ((long)row * ostride4 + coff4 + c4) * 4);
    ph[0] = h01; ph[1] = h23;
}

// ---------------------------------------------------------------------------
// Embedding: x = emb[token] + pos ; also writes fp16
// ---------------------------------------------------------------------------
__global__ void embed_kernel(const int* __restrict__ tokens,
                             const float* __restrict__ emb,
                             const float* __restrict__ pos,
                             float* __restrict__ x,
                             __half* __restrict__ xh)
{
    int row = blockIdx.x;
    int s = row & (SEQ - 1);
    int t = tokens[row];
    const float4* e = (const float4*)(emb + (long)t * DMODEL);
    const float4* p = (const float4*)(pos + (long)s * DMODEL);
    for (int d = threadIdx.x; d < DMODEL / 4; d += blockDim.x) {
        float4 a = e[d], b = p[d];
        a.x += b.x; a.y += b.y; a.z += b.z; a.w += b.w;
        long o = (long)row * DMODEL + d * 4;
        *(float4*)&x[o] = a;
        __half2 h01, h23;
        h01.x = __float2half_rn(a.x); h01.y = __float2half_rn(a.y);
        h23.x = __float2half_rn(a.z); h23.y = __float2half_rn(a.w);
        *(__half2*)&xh[o] = h01; *(__half2*)&xh[o + 2] = h23;
    }
}

// qkv bias concat
__global__ void bias_concat_kernel(const float* __restrict__ bq, const float* __restrict__ bk,
                                   const float* __restrict__ bv, float* __restrict__ out)
{
    int i = blockIdx.x * blockDim.x + threadIdx.x;
    if (i >= NLAYER * QKVN) return;
    int l = i / QKVN, c = i - l * QKVN;
    float v = (c < 1024) ? bq[l * 1024 + c]
            : (c < 2048) ? bk[l * 1024 + c - 1024]
                         : bv[l * 1024 + c - 2048];
    out[i] = v;
}

// ---------------------------------------------------------------------------
// HMMA GEMM: C[M,N] = A[M,K] @ B  (A fp16 [M,K]; B fp16 [K,N] natural)
// CTA 128x128, BK=64, 8 warps (2x4), warp tile 64x32, mma.sync m16n8k16.
// 64 MMAs per warp per barrier; 3-stage cp.async pipeline; 2 CTAs/SM.
// ---------------------------------------------------------------------------
#define ASTRIDE 144                 // A smem row stride bytes (64 halves + pad)
#define ATILE_B 18432               // [128][72] halves
#define BSTRIDE 272                 // B smem row stride bytes (128 halves + pad)
#define BTILE_B 17408               // [64][136] halves
#define STAGE_B (ATILE_B + BTILE_B)       // 35840
#define GEMM_SMEM (3 * STAGE_B)           // 107520 (x2 CTAs = 215040 < 228KB)

template<bool RELU, bool RESID, bool WF32, bool WH16>
__global__ __launch_bounds__(256, 2)
void hmma_gemm(const __half* __restrict__ A, const __half* __restrict__ B,
               const float* __restrict__ bias, const float* __restrict__ resid,
               float* __restrict__ Cf, __half* __restrict__ Ch,
               int N, int K)
{
    extern __shared__ char smem[];
    uint32_t sbase = smem_u32(smem);

    int tid = threadIdx.x;
    int lane = tid & 31;
    int wid = tid >> 5;
    int wm = wid & 1;          // 2 warps over M (64 rows each)
    int wn = wid >> 1;         // 4 warps over N (32 cols each)
    int row0 = blockIdx.x * 128;
    int ncol0 = blockIdx.y * 128;
    int nk = K >> 6;           // BK=64 chunks (K >= 1024 here)

    float c[4][4][4];
#pragma unroll
    for (int i = 0; i < 4; i++)
#pragma unroll
        for (int j = 0; j < 4; j++)
#pragma unroll
            for (int k = 0; k < 4; k++) c[i][j][k] = 0.f;

    auto load_stage = [&](int chunk, int buf) {
        uint32_t sb = sbase + buf * STAGE_B;
        int kc = chunk << 6;
        // A: 128 rows x 128B (1024 cp)
#pragma unroll 4
        for (int i = tid; i < 1024; i += 256) {
            int r = i >> 3, sg = i & 7;
            cp_async16(sb + (uint32_t)(r * ASTRIDE + sg * 16),
                       A + (long)(row0 + r) * K + kc + sg * 8);
        }
        // B: 64 k-rows x 256B (1024 cp)
#pragma unroll 4
        for (int i = tid; i < 1024; i += 256) {
            int r = i >> 4, cc = i & 15;
            cp_async16(sb + ATILE_B + (uint32_t)(r * BSTRIDE + cc * 16),
                       B + (long)(kc + r) * N + ncol0 + cc * 8);
        }
        cp_commit();
    };

    load_stage(0, 0);
    load_stage(1, 1);

    // A ldmatrix addressing (row-major, non-trans)
    int arow = (lane & 7) + ((lane >> 3) & 1) * 8;
    int akk = ((lane >> 4) & 1) * 8;
    // B ldmatrix addressing (trans): group t = lane/8
    int bt = lane >> 3, br = lane & 7;
    int brow_off = (bt & 1) * 8 + br;       // k within 16
    int bcol_off = (bt >> 1) * 8;           // n within 16

    int buf = 0;
    for (int ch = 0; ch < nk; ch++) {
        if (ch + 1 < nk) cp_wait<1>(); else cp_wait<0>();
        __syncthreads();
        if (ch + 2 < nk) {
            int nb = buf + 2; if (nb >= 3) nb -= 3;
            load_stage(ch + 2, nb);
        }

        uint32_t sb = sbase + buf * STAGE_B;
#pragma unroll
        for (int ks = 0; ks < 4; ks++) {
            int k0 = ks * 16;
            uint32_t a_r[4][4], b_r[4][2];
#pragma unroll
            for (int mi = 0; mi < 4; mi++) {
                uint32_t ad = sb + (uint32_t)((wm * 64 + mi * 16 + arow) * ASTRIDE
                                              + (k0 + akk) * 2);
                ldsm_x4(a_r[mi], ad);
            }
#pragma unroll
            for (int p = 0; p < 2; p++) {
                uint32_t bd = sb + ATILE_B
                            + (uint32_t)((k0 + brow_off) * BSTRIDE
                                         + (wn * 32 + p * 16 + bcol_off) * 2);
                uint32_t r[4];
                ldsm_x4_trans(r, bd);
                b_r[2 * p][0] = r[0]; b_r[2 * p][1] = r[1];
                b_r[2 * p + 1][0] = r[2]; b_r[2 * p + 1][1] = r[3];
            }
#pragma unroll
            for (int mi = 0; mi < 4; mi++)
#pragma unroll
                for (int ni = 0; ni < 4; ni++)
                    mma_f16(c[mi][ni], a_r[mi], b_r[ni]);
        }
        if (++buf == 3) buf = 0;
    }

    // Epilogue
    int rbase = row0 + wm * 64 + (lane >> 2);
    int cbase = ncol0 + wn * 32 + (lane & 3) * 2;
#pragma unroll
    for (int mi = 0; mi < 4; mi++) {
#pragma unroll
        for (int ni = 0; ni < 4; ni++) {
            int gc = cbase + ni * 8;
            float b0 = __ldg(&bias[gc]), b1 = __ldg(&bias[gc + 1]);
#pragma unroll
            for (int half_ = 0; half_ < 2; half_++) {
                long gr = rbase + mi * 16 + half_ * 8;
                float v0 = c[mi][ni][half_ * 2 + 0] + b0;
                float v1 = c[mi][ni][half_ * 2 + 1] + b1;
                if (RELU) { v0 = fmaxf(v0, 0.f); v1 = fmaxf(v1, 0.f); }
                if (RESID) {
                    float2 rr = *(const float2*)&resid[gr * N + gc];
                    v0 += rr.x; v1 += rr.y;
                }
                if (WF32) {
                    float2 o; o.x = v0; o.y = v1;
                    *(float2*)&Cf[gr * N + gc] = o;
                }
                if (WH16) {
                    __half2 hh;
                    hh.x = __float2half_rn(v0); hh.y = __float2half_rn(v1);
                    *(__half2*)&Ch[gr * N + gc] = hh;
                }
            }
        }
    }
}

// ---------------------------------------------------------------------------
// Flash attention (fp32), reads fused qkv [M,3072], writes fp16 attn out
// ---------------------------------------------------------------------------
#define FPAD 68

__global__ __launch_bounds__(256)
void flash_attn_kernel(const float* __restrict__ QKV,
                       __half* __restrict__ Ao)
{
    extern __shared__ float sm[];
    float* Qs = sm;
    float* Ks = sm + 64 * FPAD;
    float* Vs = sm + 2 * 64 * FPAD;
    float* Ps = sm + 3 * 64 * FPAD;

    int qt = gridDim.x - 1 - blockIdx.x;
    int bh = blockIdx.y;
    int b = bh >> 4;
    int h = bh & 15;
    int tid = threadIdx.x;
    int tx = tid & 15;
    int ty = tid >> 4;

    long baseq = (long)b * SEQ * QKVN + h * HDIM;
    long basek = baseq + 1024;
    long basev = baseq + 2048;

    for (int i = tid; i < 64 * 16; i += 256) {
        int r = i >> 4, c4 = (i & 15) * 4;
        *(float4*)&Qs[r * FPAD + c4] =
            *(const float4*)&QKV[baseq + (long)(qt * 64 + r) * QKVN + c4];
    }

    float m[4], l[4], o[4][4];
#pragma unroll
    for (int i = 0; i < 4; i++) {
        m[i] = -1e30f; l[i] = 0.f;
#pragma unroll
        for (int j = 0; j < 4; j++) o[i][j] = 0.f;
    }

    for (int jt = 0; jt <= qt; jt++) {
        for (int i = tid; i < 64 * 16; i += 256) {
            int r = i >> 4, c4 = (i & 15) * 4;
            long off = (long)(jt * 64 + r) * QKVN + c4;
            *(float4*)&Ks[r * FPAD + c4] = *(const float4*)&QKV[basek + off];
            *(float4*)&Vs[r * FPAD + c4] = *(const float4*)&QKV[basev + off];
        }
        __syncthreads();

        float s[4][4];
#pragma unroll
        for (int i = 0; i < 4; i++)
#pragma unroll
            for (int j = 0; j < 4; j++) s[i][j] = 0.f;

#pragma unroll 4
        for (int k4 = 0; k4 < HDIM; k4 += 4) {
            float4 qv[4], kv[4];
#pragma unroll
            for (int i = 0; i < 4; i++)
                qv[i] = *(const float4*)&Qs[(ty * 4 + i) * FPAD + k4];
#pragma unroll
            for (int j = 0; j < 4; j++)
                kv[j] = *(const float4*)&Ks[(tx + 16 * j) * FPAD + k4];
#pragma unroll
            for (int i = 0; i < 4; i++)
#pragma unroll
                for (int j = 0; j < 4; j++) {
                    s[i][j] = fmaf(qv[i].x, kv[j].x, s[i][j]);
                    s[i][j] = fmaf(qv[i].y, kv[j].y, s[i][j]);
                    s[i][j] = fmaf(qv[i].z, kv[j].z, s[i][j]);
                    s[i][j] = fmaf(qv[i].w, kv[j].w, s[i][j]);
                }
        }

        if (jt == qt) {
#pragma unroll
            for (int i = 0; i < 4; i++) {
                int qloc = ty * 4 + i;
#pragma unroll
                for (int j = 0; j < 4; j++) {
                    int kloc = tx + 16 * j;
                    s[i][j] = (kloc > qloc) ? -1e30f : s[i][j] * 0.125f;
                }
            }
        } else {
#pragma unroll
            for (int i = 0; i < 4; i++)
#pragma unroll
                for (int j = 0; j < 4; j++) s[i][j] *= 0.125f;
        }

#pragma unroll
        for (int i = 0; i < 4; i++) {
            float rmax = fmaxf(fmaxf(s[i][0], s[i][1]), fmaxf(s[i][2], s[i][3]));
#pragma unroll
            for (int w = 1; w < 16; w <<= 1)
                rmax = fmaxf(rmax, __shfl_xor_sync(0xffffffffu, rmax, w));
            float mn = fmaxf(m[i], rmax);
            float corr = __expf(m[i] - mn);
            float rsum = 0.f;
#pragma unroll
            for (int j = 0; j < 4; j++) {
                float p = __expf(s[i][j] - mn);
                s[i][j] = p;
                rsum += p;
            }
#pragma unroll
            for (int w = 1; w < 16; w <<= 1)
                rsum += __shfl_xor_sync(0xffffffffu, rsum, w);
            l[i] = l[i] * corr + rsum;
            m[i] = mn;
#pragma unroll
            for (int j = 0; j < 4; j++) o[i][j] *= corr;
        }

#pragma unroll
        for (int i = 0; i < 4; i++)
#pragma unroll
            for (int j = 0; j < 4; j++)
                Ps[(ty * 4 + i) * FPAD + tx + 16 * j] = s[i][j];
        __syncthreads();

#pragma unroll 4
        for (int k4 = 0; k4 < 64; k4 += 4) {
            float4 pv[4];
#pragma unroll
            for (int i = 0; i < 4; i++)
                pv[i] = *(const float4*)&Ps[(ty * 4 + i) * FPAD + k4];
#pragma unroll
            for (int cc = 0; cc < 4; cc++) {
                float4 vv = *(const float4*)&Vs[(k4 + cc) * FPAD + tx * 4];
#pragma unroll
                for (int i = 0; i < 4; i++) {
                    float p = (cc == 0) ? pv[i].x : (cc == 1) ? pv[i].y
                              : (cc == 2) ? pv[i].z : pv[i].w;
                    o[i][0] = fmaf(p, vv.x, o[i][0]);
                    o[i][1] = fmaf(p, vv.y, o[i][1]);
                    o[i][2] = fmaf(p, vv.z, o[i][2]);
                    o[i][3] = fmaf(p, vv.w, o[i][3]);
                }
            }
        }
        __syncthreads();
    }

#pragma unroll
    for (int i = 0; i < 4; i++) {
        float inv = 1.0f / l[i];
        int qg = qt * 64 + ty * 4 + i;
        __half2 h01, h23;
        h01.x = __float2half_rn(o[i][0] * inv);
        h01.y = __float2half_rn(o[i][1] * inv);
        h23.x = __float2half_rn(o[i][2] * inv);
        h23.y = __float2half_rn(o[i][3] * inv);
        long oaddr = (long)(b * SEQ + qg) * HK + h * HDIM + tx * 4;
        *(__half2*)&Ao[oaddr] = h01; *(__half2*)&Ao[oaddr + 2] = h23;
    }
}

#define FLASH_SMEM (4 * 64 * FPAD * 4)

// ---------------------------------------------------------------------------
// Launch
// ---------------------------------------------------------------------------
extern "C" void kernel_launch(void* const* d_in, const int* in_sizes, int n_in,
                              void* d_out, int out_size)
{
    const int*   tokens = (const int*)  d_in[0];
    const float* emb    = (const float*)d_in[1];
    const float* pos    = (const float*)d_in[2];
    const float* Wq     = (const float*)d_in[3];
    const float* bq     = (const float*)d_in[4];
    const float* Wk     = (const float*)d_in[5];
    const float* bk     = (const float*)d_in[6];
    const float* Wv     = (const float*)d_in[7];
    const float* bv     = (const float*)d_in[8];
    const float* Wo     = (const float*)d_in[9];
    const float* bo     = (const float*)d_in[10];
    const float* W1     = (const float*)d_in[11];
    const float* b1     = (const float*)d_in[12];
    const float* W2     = (const float*)d_in[13];
    const float* b2     = (const float*)d_in[14];
    const float* Wf     = (const float*)d_in[15];
    const float* bf     = (const float*)d_in[16];
    float* out = (float*)d_out;

    float *x, *qkv, *qkvb;
    __half *xh, *ah, *fh;
    __half *wqkv, *wo, *w1, *w2, *wf;
    cudaGetSymbolAddress((void**)&x, g_x);
    cudaGetSymbolAddress((void**)&qkv, g_qkv);
    cudaGetSymbolAddress((void**)&qkvb, g_qkvb);
    cudaGetSymbolAddress((void**)&xh, g_xh);
    cudaGetSymbolAddress((void**)&ah, g_ah);
    cudaGetSymbolAddress((void**)&fh, g_fh);
    cudaGetSymbolAddress((void**)&wqkv, g_wqkv);
    cudaGetSymbolAddress((void**)&wo, g_wo);
    cudaGetSymbolAddress((void**)&w1, g_w1);
    cudaGetSymbolAddress((void**)&w2, g_w2);
    cudaGetSymbolAddress((void**)&wf, g_wf);

    static bool attr_set = false;
    if (!attr_set) {
        cudaFuncSetAttribute(flash_attn_kernel,
                             cudaFuncAttributeMaxDynamicSharedMemorySize, FLASH_SMEM);
        cudaFuncSetAttribute(hmma_gemm<false, false, true, false>,
                             cudaFuncAttributeMaxDynamicSharedMemorySize, GEMM_SMEM);
        cudaFuncSetAttribute(hmma_gemm<false, true, true, true>,
                             cudaFuncAttributeMaxDynamicSharedMemorySize, GEMM_SMEM);
        cudaFuncSetAttribute(hmma_gemm<true, false, false, true>,
                             cudaFuncAttributeMaxDynamicSharedMemorySize, GEMM_SMEM);
        attr_set = true;
    }

    // ---- weight convert (no transpose; [K,N] natural layout) ----
    for (int l = 0; l < NLAYER; l++) {
        wsplit_kernel<<<dim3(DMODEL, 1), 256>>>(Wq + (long)l * DMODEL * HK,
            wqkv + (long)l * DMODEL * QKVN, HK / 4, QKVN / 4, 0);
        wsplit_kernel<<<dim3(DMODEL, 1), 256>>>(Wk + (long)l * DMODEL * HK,
            wqkv + (long)l * DMODEL * QKVN, HK / 4, QKVN / 4, 1024 / 4);
        wsplit_kernel<<<dim3(DMODEL, 1), 256>>>(Wv + (long)l * DMODEL * HK,
            wqkv + (long)l * DMODEL * QKVN, HK / 4, QKVN / 4, 2048 / 4);
        wsplit_kernel<<<dim3(HK, 1), 256>>>(Wo + (long)l * HK * DMODEL,
            wo + (long)l * HK * DMODEL, DMODEL / 4, DMODEL / 4, 0);
        wsplit_kernel<<<dim3(DMODEL, 4), 256>>>(W1 + (long)l * DMODEL * FFDIM,
            w1 + (long)l * DMODEL * FFDIM, FFDIM / 4, FFDIM / 4, 0);
        wsplit_kernel<<<dim3(FFDIM, 1), 256>>>(W2 + (long)l * FFDIM * DMODEL,
            w2 + (long)l * FFDIM * DMODEL, DMODEL / 4, DMODEL / 4, 0);
    }
    wsplit_kernel<<<dim3(DMODEL, 32), 256>>>(Wf, wf, VOCAB / 4, VOCAB / 4, 0);
    bias_concat_kernel<<<(NLAYER * QKVN + 255) / 256, 256>>>(bq, bk, bv, qkvb);

    // ---- forward ----
    embed_kernel<<<MTOK, 256>>>(tokens, emb, pos, x, xh);

    dim3 gQKV(MTOK / 128, QKVN / 128);
    dim3 gProj(MTOK / 128, DMODEL / 128);
    dim3 gFF1(MTOK / 128, FFDIM / 128);
    dim3 gLogits(MTOK / 128, VOCAB / 128);
    dim3 gAttn(SEQ / 64, BATCH * NHEAD);

    for (int l = 0; l < NLAYER; l++) {
        // qkv = x @ Wqkv + b  (fp32 out)
        hmma_gemm<false, false, true, false><<<gQKV, 256, GEMM_SMEM>>>(
            xh, wqkv + (long)l * DMODEL * QKVN, qkvb + (long)l * QKVN, nullptr,
            qkv, nullptr, QKVN, DMODEL);

        flash_attn_kernel<<<gAttn, 256, FLASH_SMEM>>>(qkv, ah);

        // x = x + a @ Wo + bo  (fp32 + fp16 out)
        hmma_gemm<false, true, true, true><<<gProj, 256, GEMM_SMEM>>>(
            ah, wo + (long)l * HK * DMODEL,
            bo + (long)l * DMODEL, x, x, xh, DMODEL, HK);

        // f = relu(x @ W1 + b1)  (fp16 only)
        hmma_gemm<true, false, false, true><<<gFF1, 256, GEMM_SMEM>>>(
            xh, w1 + (long)l * DMODEL * FFDIM,
            b1 + (long)l * FFDIM, nullptr, nullptr, fh, FFDIM, DMODEL);

        // x = x + f @ W2 + b2
        hmma_gemm<false, true, true, true><<<gProj, 256, GEMM_SMEM>>>(
            fh, w2 + (long)l * FFDIM * DMODEL,
            b2 + (long)l * DMODEL, x, x, xh, DMODEL, FFDIM);
    }

    // logits = x @ Wf + bf
    hmma_gemm<false, false, true, false><<<gLogits, 256, GEMM_SMEM>>>(
        xh, wf, bf, nullptr, out, nullptr, VOCAB, DMODEL);
}

// round 11
// speedup vs baseline: 1.8578x; 1.7068x over previous
#include <cuda_runtime.h>
#include <cuda_fp16.h>
#include <cstdint>

// Problem constants
#define VOCAB 32000
#define DMODEL 1024
#define NHEAD 16
#define HDIM 64
#define FFDIM 4096
#define NLAYER 4
#define SEQ 2048
#define BATCH 2
#define MTOK (BATCH * SEQ)      // 4096 token rows
#define HK (NHEAD * HDIM)       // 1024
#define QKVN 3072               // fused q|k|v output width

// ---------------------------------------------------------------------------
// Scratch (device globals; no allocations allowed)
// ---------------------------------------------------------------------------
__device__ float g_x[MTOK * DMODEL];                 // residual stream fp32
__device__ float g_qkvb[NLAYER * QKVN];              // fused qkv bias
__device__ __half g_qkvh[MTOK * QKVN];               // fused qkv fp16
__device__ __half g_xh[MTOK * DMODEL];               // activations fp16
__device__ __half g_ah[MTOK * HK];
__device__ __half g_fh[MTOK * FFDIM];
// fp16 weights, NATURAL [K,N] layout
__device__ __half g_wqkv[NLAYER * DMODEL * QKVN];
__device__ __half g_wo[NLAYER * HK * DMODEL];
__device__ __half g_w1[NLAYER * DMODEL * FFDIM];
__device__ __half g_w2[NLAYER * FFDIM * DMODEL];
__device__ __half g_wf[DMODEL * VOCAB];

// ---------------------------------------------------------------------------
// PTX helpers (all sm_80-era, arch-portable)
// ---------------------------------------------------------------------------
__device__ __forceinline__ uint32_t smem_u32(const void* p) {
    return (uint32_t)__cvta_generic_to_shared(p);
}
__device__ __forceinline__ void cp_async16(uint32_t dst, const void* src) {
    asm volatile("cp.async.cg.shared.global [%0], [%1], 16;\n" :: "r"(dst), "l"(src));
}
__device__ __forceinline__ void cp_commit() { asm volatile("cp.async.commit_group;\n" ::: "memory"); }
template<int N> __device__ __forceinline__ void cp_wait() {
    asm volatile("cp.async.wait_group %0;\n" :: "n"(N) : "memory");
}
__device__ __forceinline__ void ldsm_x4(uint32_t* r, uint32_t addr) {
    asm volatile("ldmatrix.sync.aligned.m8n8.x4.shared.b16 {%0,%1,%2,%3}, [%4];"
                 : "=r"(r[0]), "=r"(r[1]), "=r"(r[2]), "=r"(r[3]) : "r"(addr));
}
__device__ __forceinline__ void ldsm_x4_trans(uint32_t* r, uint32_t addr) {
    asm volatile("ldmatrix.sync.aligned.m8n8.x4.trans.shared.b16 {%0,%1,%2,%3}, [%4];"
                 : "=r"(r[0]), "=r"(r[1]), "=r"(r[2]), "=r"(r[3]) : "r"(addr));
}
__device__ __forceinline__ void mma_f16(float* c, const uint32_t* a, const uint32_t* b) {
    asm volatile(
        "mma.sync.aligned.m16n8k16.row.col.f32.f16.f16.f32 "
        "{%0,%1,%2,%3}, {%4,%5,%6,%7}, {%8,%9}, {%0,%1,%2,%3};"
        : "+f"(c[0]), "+f"(c[1]), "+f"(c[2]), "+f"(c[3])
        : "r"(a[0]), "r"(a[1]), "r"(a[2]), "r"(a[3]), "r"(b[0]), "r"(b[1]));
}

// ---------------------------------------------------------------------------
// Weight convert (NO transpose): W [K,N] fp32 -> fp16 [K,N], optional col pack.
// ---------------------------------------------------------------------------
__global__ void wsplit_kernel(const float* __restrict__ W,
                              __half* __restrict__ Wh,
                              int ncols4, int ostride4, int coff4)
{
    int row = blockIdx.x;
    int c4 = blockIdx.y * blockDim.x + threadIdx.x;
    if (c4 >= ncols4) return;
    float4 v = *(const float4*)(W + ((long)row * ncols4 + c4) * 4);
    __half2 h01, h23;
    h01.x = __float2half_rn(v.x); h01.y = __float2half_rn(v.y);
    h23.x = __float2half_rn(v.z); h23.y = __float2half_rn(v.w);
    __half2* ph = (__half2*)(Wh + ((long)row * ostride4 + coff4 + c4) * 4);
    ph[0] = h01; ph[1] = h23;
}

// ---------------------------------------------------------------------------
// Embedding: x = emb[token] + pos ; also writes fp16
// ---------------------------------------------------------------------------
__global__ void embed_kernel(const int* __restrict__ tokens,
                             const float* __restrict__ emb,
                             const float* __restrict__ pos,
                             float* __restrict__ x,
                             __half* __restrict__ xh)
{
    int row = blockIdx.x;
    int s = row & (SEQ - 1);
    int t = tokens[row];
    const float4* e = (const float4*)(emb + (long)t * DMODEL);
    const float4* p = (const float4*)(pos + (long)s * DMODEL);
    for (int d = threadIdx.x; d < DMODEL / 4; d += blockDim.x) {
        float4 a = e[d], b = p[d];
        a.x += b.x; a.y += b.y; a.z += b.z; a.w += b.w;
        long o = (long)row * DMODEL + d * 4;
        *(float4*)&x[o] = a;
        __half2 h01, h23;
        h01.x = __float2half_rn(a.x); h01.y = __float2half_rn(a.y);
        h23.x = __float2half_rn(a.z); h23.y = __float2half_rn(a.w);
        *(__half2*)&xh[o] = h01; *(__half2*)&xh[o + 2] = h23;
    }
}

// qkv bias concat
__global__ void bias_concat_kernel(const float* __restrict__ bq, const float* __restrict__ bk,
                                   const float* __restrict__ bv, float* __restrict__ out)
{
    int i = blockIdx.x * blockDim.x + threadIdx.x;
    if (i >= NLAYER * QKVN) return;
    int l = i / QKVN, c = i - l * QKVN;
    float v = (c < 1024) ? bq[l * 1024 + c]
            : (c < 2048) ? bk[l * 1024 + c - 1024]
                         : bv[l * 1024 + c - 2048];
    out[i] = v;
}

// ---------------------------------------------------------------------------
// HMMA GEMM: C[M,N] = A[M,K] @ B  (A fp16 [M,K]; B fp16 [K,N] natural)
// CTA 128x128, BK=64, 8 warps (2x4), warp tile 64x32, mma.sync m16n8k16.
// 3-stage cp.async pipeline; 2 CTAs/SM.
// ---------------------------------------------------------------------------
#define ASTRIDE 144                 // A smem row stride bytes (64 halves + pad)
#define ATILE_B 18432               // [128][72] halves
#define BSTRIDE 272                 // B smem row stride bytes (128 halves + pad)
#define BTILE_B 17408               // [64][136] halves
#define STAGE_B (ATILE_B + BTILE_B)       // 35840
#define GEMM_SMEM (3 * STAGE_B)           // 107520

template<bool RELU, bool RESID, bool WF32, bool WH16>
__global__ __launch_bounds__(256, 2)
void hmma_gemm(const __half* __restrict__ A, const __half* __restrict__ B,
               const float* __restrict__ bias, const float* __restrict__ resid,
               float* __restrict__ Cf, __half* __restrict__ Ch,
               int N, int K)
{
    extern __shared__ char smem[];
    uint32_t sbase = smem_u32(smem);

    int tid = threadIdx.x;
    int lane = tid & 31;
    int wid = tid >> 5;
    int wm = wid & 1;
    int wn = wid >> 1;
    int row0 = blockIdx.x * 128;
    int ncol0 = blockIdx.y * 128;
    int nk = K >> 6;

    float c[4][4][4];
#pragma unroll
    for (int i = 0; i < 4; i++)
#pragma unroll
        for (int j = 0; j < 4; j++)
#pragma unroll
            for (int k = 0; k < 4; k++) c[i][j][k] = 0.f;

    auto load_stage = [&](int chunk, int buf) {
        uint32_t sb = sbase + buf * STAGE_B;
        int kc = chunk << 6;
#pragma unroll 4
        for (int i = tid; i < 1024; i += 256) {
            int r = i >> 3, sg = i & 7;
            cp_async16(sb + (uint32_t)(r * ASTRIDE + sg * 16),
                       A + (long)(row0 + r) * K + kc + sg * 8);
        }
#pragma unroll 4
        for (int i = tid; i < 1024; i += 256) {
            int r = i >> 4, cc = i & 15;
            cp_async16(sb + ATILE_B + (uint32_t)(r * BSTRIDE + cc * 16),
                       B + (long)(kc + r) * N + ncol0 + cc * 8);
        }
        cp_commit();
    };

    load_stage(0, 0);
    load_stage(1, 1);

    int arow = (lane & 7) + ((lane >> 3) & 1) * 8;
    int akk = ((lane >> 4) & 1) * 8;
    int bt = lane >> 3, br = lane & 7;
    int brow_off = (bt & 1) * 8 + br;
    int bcol_off = (bt >> 1) * 8;

    int buf = 0;
    for (int ch = 0; ch < nk; ch++) {
        if (ch + 1 < nk) cp_wait<1>(); else cp_wait<0>();
        __syncthreads();
        if (ch + 2 < nk) {
            int nb = buf + 2; if (nb >= 3) nb -= 3;
            load_stage(ch + 2, nb);
        }

        uint32_t sb = sbase + buf * STAGE_B;
#pragma unroll
        for (int ks = 0; ks < 4; ks++) {
            int k0 = ks * 16;
            uint32_t a_r[4][4], b_r[4][2];
#pragma unroll
            for (int mi = 0; mi < 4; mi++) {
                uint32_t ad = sb + (uint32_t)((wm * 64 + mi * 16 + arow) * ASTRIDE
                                              + (k0 + akk) * 2);
                ldsm_x4(a_r[mi], ad);
            }
#pragma unroll
            for (int p = 0; p < 2; p++) {
                uint32_t bd = sb + ATILE_B
                            + (uint32_t)((k0 + brow_off) * BSTRIDE
                                         + (wn * 32 + p * 16 + bcol_off) * 2);
                uint32_t r[4];
                ldsm_x4_trans(r, bd);
                b_r[2 * p][0] = r[0]; b_r[2 * p][1] = r[1];
                b_r[2 * p + 1][0] = r[2]; b_r[2 * p + 1][1] = r[3];
            }
#pragma unroll
            for (int mi = 0; mi < 4; mi++)
#pragma unroll
                for (int ni = 0; ni < 4; ni++)
                    mma_f16(c[mi][ni], a_r[mi], b_r[ni]);
        }
        if (++buf == 3) buf = 0;
    }

    int rbase = row0 + wm * 64 + (lane >> 2);
    int cbase = ncol0 + wn * 32 + (lane & 3) * 2;
#pragma unroll
    for (int mi = 0; mi < 4; mi++) {
#pragma unroll
        for (int ni = 0; ni < 4; ni++) {
            int gc = cbase + ni * 8;
            float b0 = __ldg(&bias[gc]), b1 = __ldg(&bias[gc + 1]);
#pragma unroll
            for (int half_ = 0; half_ < 2; half_++) {
                long gr = rbase + mi * 16 + half_ * 8;
                float v0 = c[mi][ni][half_ * 2 + 0] + b0;
                float v1 = c[mi][ni][half_ * 2 + 1] + b1;
                if (RELU) { v0 = fmaxf(v0, 0.f); v1 = fmaxf(v1, 0.f); }
                if (RESID) {
                    float2 rr = *(const float2*)&resid[gr * N + gc];
                    v0 += rr.x; v1 += rr.y;
                }
                if (WF32) {
                    float2 o; o.x = v0; o.y = v1;
                    *(float2*)&Cf[gr * N + gc] = o;
                }
                if (WH16) {
                    __half2 hh;
                    hh.x = __float2half_rn(v0); hh.y = __float2half_rn(v1);
                    *(__half2*)&Ch[gr * N + gc] = hh;
                }
            }
        }
    }
}

// ---------------------------------------------------------------------------
// HMMA flash attention. CTA = 128 q-rows x one head. 8 warps x 16 rows.
// Reads fused qkv fp16 [M,3072]; writes attention out fp16 [M,1024].
// S = Q@K^T via non-trans ldsm on K ([N,K] layout — round-4-proven mapping).
// O += P@V via trans ldsm on V ([K,N] layout — current-GEMM-proven mapping).
// P reuses S accumulator registers as A fragments (C->A identity).
// ---------------------------------------------------------------------------
#define FSTR 144   // smem row stride bytes (64 halves + 8 pad)
#define FQ_B (128 * FSTR)          // 18432
#define FK_B (64 * FSTR)           // 9216
#define FLASH_SMEM2 (FQ_B + 2 * FK_B)  // 36864

__global__ __launch_bounds__(256, 2)
void flash_attn_hmma(const __half* __restrict__ QKV, __half* __restrict__ Ao)
{
    extern __shared__ char sm8[];
    uint32_t sq = smem_u32(sm8);
    uint32_t sk = sq + FQ_B;
    uint32_t sv = sk + FK_B;

    int qt = gridDim.x - 1 - blockIdx.x;     // heavy tiles first
    int bh = blockIdx.y;
    int b = bh >> 4, h = bh & 15;
    int tid = threadIdx.x, lane = tid & 31, wid = tid >> 5;

    const __half* Qg = QKV + (long)b * SEQ * QKVN + h * HDIM;
    const __half* Kg = Qg + 1024;
    const __half* Vg = Qg + 2048;

    // Load Q tile: 128 rows x 128B
    for (int i = tid; i < 1024; i += 256) {
        int r = i >> 3, sg = i & 7;
        cp_async16(sq + (uint32_t)(r * FSTR + sg * 16),
                   Qg + (long)(qt * 128 + r) * QKVN + sg * 8);
    }
    cp_commit();

    int arow = (lane & 7) + ((lane >> 3) & 1) * 8;
    int akk = ((lane >> 4) & 1) * 8;
    int bt = lane >> 3, br = lane & 7;
    int brow_off = (bt & 1) * 8 + br;
    int bcol_off = (bt >> 1) * 8;

    cp_wait<0>();
    __syncthreads();

    // Q fragments held in registers for the whole kernel
    uint32_t a_q[4][4];
#pragma unroll
    for (int ks = 0; ks < 4; ks++)
        ldsm_x4(a_q[ks], sq + (uint32_t)((wid * 16 + arow) * FSTR + (ks * 16 + akk) * 2));

    float o[8][4];
#pragma unroll
    for (int i = 0; i < 8; i++)
#pragma unroll
        for (int j = 0; j < 4; j++) o[i][j] = 0.f;
    float m_[2] = {-1e30f, -1e30f}, l_[2] = {0.f, 0.f};

    int rloc = wid * 16 + (lane >> 2);       // local row (first half)
    int r0g = qt * 128 + rloc;               // global q row (first half)
    int njt = 2 * qt + 2;

    for (int jt = 0; jt < njt; jt++) {
        __syncthreads();   // everyone done with previous K/V
        for (int i = tid; i < 512; i += 256) {
            int r = i >> 3, sg = i & 7;
            long g = (long)(jt * 64 + r) * QKVN + sg * 8;
            cp_async16(sk + (uint32_t)(r * FSTR + sg * 16), Kg + g);
            cp_async16(sv + (uint32_t)(r * FSTR + sg * 16), Vg + g);
        }
        cp_commit();
        cp_wait<0>();
        __syncthreads();

        // ---- S = Q @ K^T ----
        float cs[8][4];
#pragma unroll
        for (int i = 0; i < 8; i++)
#pragma unroll
            for (int j = 0; j < 4; j++) cs[i][j] = 0.f;

#pragma unroll
        for (int ks = 0; ks < 4; ks++) {
            uint32_t b_r[8][2];
#pragma unroll
            for (int p = 0; p < 4; p++) {
                uint32_t r[4];
                ldsm_x4(r, sk + (uint32_t)((p * 16 + arow) * FSTR + (ks * 16 + akk) * 2));
                b_r[2 * p][0] = r[0]; b_r[2 * p + 1][0] = r[1];
                b_r[2 * p][1] = r[2]; b_r[2 * p + 1][1] = r[3];
            }
#pragma unroll
            for (int ni = 0; ni < 8; ni++)
                mma_f16(cs[ni], a_q[ks], b_r[ni]);
        }

        // ---- scale + causal mask ----
        bool need_mask = (jt * 64 + 63) > (qt * 128 + wid * 16);
        if (need_mask) {
#pragma unroll
            for (int ni = 0; ni < 8; ni++) {
                int k0c = jt * 64 + ni * 8 + (lane & 3) * 2;
#pragma unroll
                for (int hf = 0; hf < 2; hf++) {
                    int qrow = r0g + hf * 8;
                    float v0 = cs[ni][hf * 2 + 0] * 0.125f;
                    float v1 = cs[ni][hf * 2 + 1] * 0.125f;
                    cs[ni][hf * 2 + 0] = (k0c > qrow) ? -1e30f : v0;
                    cs[ni][hf * 2 + 1] = (k0c + 1 > qrow) ? -1e30f : v1;
                }
            }
        } else {
#pragma unroll
            for (int ni = 0; ni < 8; ni++)
#pragma unroll
                for (int j = 0; j < 4; j++) cs[ni][j] *= 0.125f;
        }

        // ---- online softmax (per row; quad-local reduce) ----
#pragma unroll
        for (int hf = 0; hf < 2; hf++) {
            float mx = m_[hf];
#pragma unroll
            for (int ni = 0; ni < 8; ni++)
                mx = fmaxf(mx, fmaxf(cs[ni][hf * 2], cs[ni][hf * 2 + 1]));
            mx = fmaxf(mx, __shfl_xor_sync(0xffffffffu, mx, 1));
            mx = fmaxf(mx, __shfl_xor_sync(0xffffffffu, mx, 2));
            float corr = __expf(m_[hf] - mx);
            float rsum = 0.f;
#pragma unroll
            for (int ni = 0; ni < 8; ni++) {
                float p0 = __expf(cs[ni][hf * 2 + 0] - mx);
                float p1 = __expf(cs[ni][hf * 2 + 1] - mx);
                cs[ni][hf * 2 + 0] = p0;
                cs[ni][hf * 2 + 1] = p1;
                rsum += p0 + p1;
            }
            rsum += __shfl_xor_sync(0xffffffffu, rsum, 1);
            rsum += __shfl_xor_sync(0xffffffffu, rsum, 2);
            l_[hf] = l_[hf] * corr + rsum;
            m_[hf] = mx;
#pragma unroll
            for (int ni = 0; ni < 8; ni++) {
                o[ni][hf * 2 + 0] *= corr;
                o[ni][hf * 2 + 1] *= corr;
            }
        }

        // ---- O += P @ V ----
#pragma unroll
        for (int ks2 = 0; ks2 < 4; ks2++) {
            uint32_t a_p[4];
            {
                __half2 t0 = __floats2half2_rn(cs[2 * ks2][0], cs[2 * ks2][1]);
                __half2 t1 = __floats2half2_rn(cs[2 * ks2][2], cs[2 * ks2][3]);
                __half2 t2 = __floats2half2_rn(cs[2 * ks2 + 1][0], cs[2 * ks2 + 1][1]);
                __half2 t3 = __floats2half2_rn(cs[2 * ks2 + 1][2], cs[2 * ks2 + 1][3]);
                a_p[0] = *(uint32_t*)&t0; a_p[1] = *(uint32_t*)&t1;
                a_p[2] = *(uint32_t*)&t2; a_p[3] = *(uint32_t*)&t3;
            }
            uint32_t b_v[8][2];
#pragma unroll
            for (int p = 0; p < 4; p++) {
                uint32_t r[4];
                ldsm_x4_trans(r, sv + (uint32_t)((ks2 * 16 + brow_off) * FSTR
                                                 + (p * 16 + bcol_off) * 2));
                b_v[2 * p][0] = r[0]; b_v[2 * p][1] = r[1];
                b_v[2 * p + 1][0] = r[2]; b_v[2 * p + 1][1] = r[3];
            }
#pragma unroll
            for (int ni = 0; ni < 8; ni++)
                mma_f16(o[ni], a_p, b_v[ni]);
        }
    }

    // ---- write O / l ----
#pragma unroll
    for (int hf = 0; hf < 2; hf++) {
        float inv = 1.0f / l_[hf];
        long row = (long)(b * SEQ + r0g + hf * 8);
#pragma unroll
        for (int ni = 0; ni < 8; ni++) {
            __half2 hv = __floats2half2_rn(o[ni][hf * 2 + 0] * inv,
                                           o[ni][hf * 2 + 1] * inv);
            *(__half2*)&Ao[row * HK + h * HDIM + ni * 8 + (lane & 3) * 2] = hv;
        }
    }
}

// ---------------------------------------------------------------------------
// Launch
// ---------------------------------------------------------------------------
extern "C" void kernel_launch(void* const* d_in, const int* in_sizes, int n_in,
                              void* d_out, int out_size)
{
    const int*   tokens = (const int*)  d_in[0];
    const float* emb    = (const float*)d_in[1];
    const float* pos    = (const float*)d_in[2];
    const float* Wq     = (const float*)d_in[3];
    const float* bq     = (const float*)d_in[4];
    const float* Wk     = (const float*)d_in[5];
    const float* bk     = (const float*)d_in[6];
    const float* Wv     = (const float*)d_in[7];
    const float* bv     = (const float*)d_in[8];
    const float* Wo     = (const float*)d_in[9];
    const float* bo     = (const float*)d_in[10];
    const float* W1     = (const float*)d_in[11];
    const float* b1     = (const float*)d_in[12];
    const float* W2     = (const float*)d_in[13];
    const float* b2     = (const float*)d_in[14];
    const float* Wf     = (const float*)d_in[15];
    const float* bf     = (const float*)d_in[16];
    float* out = (float*)d_out;

    float *x, *qkvb;
    __half *qkvh, *xh, *ah, *fh;
    __half *wqkv, *wo, *w1, *w2, *wf;
    cudaGetSymbolAddress((void**)&x, g_x);
    cudaGetSymbolAddress((void**)&qkvb, g_qkvb);
    cudaGetSymbolAddress((void**)&qkvh, g_qkvh);
    cudaGetSymbolAddress((void**)&xh, g_xh);
    cudaGetSymbolAddress((void**)&ah, g_ah);
    cudaGetSymbolAddress((void**)&fh, g_fh);
    cudaGetSymbolAddress((void**)&wqkv, g_wqkv);
    cudaGetSymbolAddress((void**)&wo, g_wo);
    cudaGetSymbolAddress((void**)&w1, g_w1);
    cudaGetSymbolAddress((void**)&w2, g_w2);
    cudaGetSymbolAddress((void**)&wf, g_wf);

    static bool attr_set = false;
    if (!attr_set) {
        cudaFuncSetAttribute(flash_attn_hmma,
                             cudaFuncAttributeMaxDynamicSharedMemorySize, FLASH_SMEM2);
        cudaFuncSetAttribute(hmma_gemm<false, false, true, false>,
                             cudaFuncAttributeMaxDynamicSharedMemorySize, GEMM_SMEM);
        cudaFuncSetAttribute(hmma_gemm<false, false, false, true>,
                             cudaFuncAttributeMaxDynamicSharedMemorySize, GEMM_SMEM);
        cudaFuncSetAttribute(hmma_gemm<false, true, true, true>,
                             cudaFuncAttributeMaxDynamicSharedMemorySize, GEMM_SMEM);
        cudaFuncSetAttribute(hmma_gemm<true, false, false, true>,
                             cudaFuncAttributeMaxDynamicSharedMemorySize, GEMM_SMEM);
        attr_set = true;
    }

    // ---- weight convert (no transpose; [K,N] natural layout) ----
    for (int l = 0; l < NLAYER; l++) {
        wsplit_kernel<<<dim3(DMODEL, 1), 256>>>(Wq + (long)l * DMODEL * HK,
            wqkv + (long)l * DMODEL * QKVN, HK / 4, QKVN / 4, 0);
        wsplit_kernel<<<dim3(DMODEL, 1), 256>>>(Wk + (long)l * DMODEL * HK,
            wqkv + (long)l * DMODEL * QKVN, HK / 4, QKVN / 4, 1024 / 4);
        wsplit_kernel<<<dim3(DMODEL, 1), 256>>>(Wv + (long)l * DMODEL * HK,
            wqkv + (long)l * DMODEL * QKVN, HK / 4, QKVN / 4, 2048 / 4);
        wsplit_kernel<<<dim3(HK, 1), 256>>>(Wo + (long)l * HK * DMODEL,
            wo + (long)l * HK * DMODEL, DMODEL / 4, DMODEL / 4, 0);
        wsplit_kernel<<<dim3(DMODEL, 4), 256>>>(W1 + (long)l * DMODEL * FFDIM,
            w1 + (long)l * DMODEL * FFDIM, FFDIM / 4, FFDIM / 4, 0);
        wsplit_kernel<<<dim3(FFDIM, 1), 256>>>(W2 + (long)l * FFDIM * DMODEL,
            w2 + (long)l * FFDIM * DMODEL, DMODEL / 4, DMODEL / 4, 0);
    }
    wsplit_kernel<<<dim3(DMODEL, 32), 256>>>(Wf, wf, VOCAB / 4, VOCAB / 4, 0);
    bias_concat_kernel<<<(NLAYER * QKVN + 255) / 256, 256>>>(bq, bk, bv, qkvb);

    // ---- forward ----
    embed_kernel<<<MTOK, 256>>>(tokens, emb, pos, x, xh);

    dim3 gQKV(MTOK / 128, QKVN / 128);
    dim3 gProj(MTOK / 128, DMODEL / 128);
    dim3 gFF1(MTOK / 128, FFDIM / 128);
    dim3 gLogits(MTOK / 128, VOCAB / 128);
    dim3 gAttn(SEQ / 128, BATCH * NHEAD);   // 16 x 32

    for (int l = 0; l < NLAYER; l++) {
        // qkv = x @ Wqkv + b  (fp16 out)
        hmma_gemm<false, false, false, true><<<gQKV, 256, GEMM_SMEM>>>(
            xh, wqkv + (long)l * DMODEL * QKVN, qkvb + (long)l * QKVN, nullptr,
            nullptr, qkvh, QKVN, DMODEL);

        flash_attn_hmma<<<gAttn, 256, FLASH_SMEM2>>>(qkvh, ah);

        // x = x + a @ Wo + bo  (fp32 + fp16 out)
        hmma_gemm<false, true, true, true><<<gProj, 256, GEMM_SMEM>>>(
            ah, wo + (long)l * HK * DMODEL,
            bo + (long)l * DMODEL, x, x, xh, DMODEL, HK);

        // f = relu(x @ W1 + b1)  (fp16 only)
        hmma_gemm<true, false, false, true><<<gFF1, 256, GEMM_SMEM>>>(
            xh, w1 + (long)l * DMODEL * FFDIM,
            b1 + (long)l * FFDIM, nullptr, nullptr, fh, FFDIM, DMODEL);

        // x = x + f @ W2 + b2
        hmma_gemm<false, true, true, true><<<gProj, 256, GEMM_SMEM>>>(
            fh, w2 + (long)l * FFDIM * DMODEL,
            b2 + (long)l * DMODEL, x, x, xh, DMODEL, FFDIM);
    }

    // logits = x @ Wf + bf
    hmma_gemm<false, false, true, false><<<gLogits, 256, GEMM_SMEM>>>(
        xh, wf, bf, nullptr, out, nullptr, VOCAB, DMODEL);
}

// round 12
// speedup vs baseline: 1.8984x; 1.0218x over previous
#include <cuda_runtime.h>
#include <cuda_fp16.h>
#include <cstdint>

// Problem constants
#define VOCAB 32000
#define DMODEL 1024
#define NHEAD 16
#define HDIM 64
#define FFDIM 4096
#define NLAYER 4
#define SEQ 2048
#define BATCH 2
#define MTOK (BATCH * SEQ)      // 4096 token rows
#define HK (NHEAD * HDIM)       // 1024
#define QKVN 3072               // fused q|k|v output width

// ---------------------------------------------------------------------------
// Scratch (device globals; no allocations allowed)
// ---------------------------------------------------------------------------
__device__ float g_x[MTOK * DMODEL];                 // residual stream fp32
__device__ float g_qkvb[NLAYER * QKVN];              // fused qkv bias
__device__ __half g_qkvh[MTOK * QKVN];               // fused qkv fp16
__device__ __half g_xh[MTOK * DMODEL];               // activations fp16
__device__ __half g_ah[MTOK * HK];
__device__ __half g_fh[MTOK * FFDIM];
// fp16 weights, NATURAL [K,N] layout
__device__ __half g_wqkv[NLAYER * DMODEL * QKVN];
__device__ __half g_wo[NLAYER * HK * DMODEL];
__device__ __half g_w1[NLAYER * DMODEL * FFDIM];
__device__ __half g_w2[NLAYER * FFDIM * DMODEL];
__device__ __half g_wf[DMODEL * VOCAB];

// ---------------------------------------------------------------------------
// PTX helpers (all sm_80-era, arch-portable)
// ---------------------------------------------------------------------------
__device__ __forceinline__ uint32_t smem_u32(const void* p) {
    return (uint32_t)__cvta_generic_to_shared(p);
}
__device__ __forceinline__ void cp_async16(uint32_t dst, const void* src) {
    asm volatile("cp.async.cg.shared.global [%0], [%1], 16;\n" :: "r"(dst), "l"(src));
}
__device__ __forceinline__ void cp_commit() { asm volatile("cp.async.commit_group;\n" ::: "memory"); }
template<int N> __device__ __forceinline__ void cp_wait() {
    asm volatile("cp.async.wait_group %0;\n" :: "n"(N) : "memory");
}
__device__ __forceinline__ void ldsm_x4(uint32_t* r, uint32_t addr) {
    asm volatile("ldmatrix.sync.aligned.m8n8.x4.shared.b16 {%0,%1,%2,%3}, [%4];"
                 : "=r"(r[0]), "=r"(r[1]), "=r"(r[2]), "=r"(r[3]) : "r"(addr));
}
__device__ __forceinline__ void ldsm_x4_trans(uint32_t* r, uint32_t addr) {
    asm volatile("ldmatrix.sync.aligned.m8n8.x4.trans.shared.b16 {%0,%1,%2,%3}, [%4];"
                 : "=r"(r[0]), "=r"(r[1]), "=r"(r[2]), "=r"(r[3]) : "r"(addr));
}
__device__ __forceinline__ void mma_f16(float* c, const uint32_t* a, const uint32_t* b) {
    asm volatile(
        "mma.sync.aligned.m16n8k16.row.col.f32.f16.f16.f32 "
        "{%0,%1,%2,%3}, {%4,%5,%6,%7}, {%8,%9}, {%0,%1,%2,%3};"
        : "+f"(c[0]), "+f"(c[1]), "+f"(c[2]), "+f"(c[3])
        : "r"(a[0]), "r"(a[1]), "r"(a[2]), "r"(a[3]), "r"(b[0]), "r"(b[1]));
}

// ---------------------------------------------------------------------------
// Flat weight convert: fp32 -> fp16, 8 elements per thread (16B store).
// ---------------------------------------------------------------------------
__global__ void wconv_flat(const float* __restrict__ W, __half* __restrict__ Wh,
                           long n8)
{
    long i = (long)blockIdx.x * blockDim.x + threadIdx.x;
    if (i >= n8) return;
    const float4* p = (const float4*)(W + i * 8);
    float4 a = p[0], b = p[1];
    __half2 h0 = __floats2half2_rn(a.x, a.y), h1 = __floats2half2_rn(a.z, a.w);
    __half2 h2 = __floats2half2_rn(b.x, b.y), h3 = __floats2half2_rn(b.z, b.w);
    uint4 o;
    o.x = *(uint32_t*)&h0; o.y = *(uint32_t*)&h1;
    o.z = *(uint32_t*)&h2; o.w = *(uint32_t*)&h3;
    *(uint4*)(Wh + i * 8) = o;
}

// Packed qkv convert: in rows of HK, out rows of QKVN at column offset coff.
// grid.x = NLAYER*DMODEL rows, 128 threads (HK/8 = 128 groups of 8).
__global__ void wconv_qkv(const float* __restrict__ W, __half* __restrict__ Wh,
                          int coff)
{
    long row = blockIdx.x;
    int t = threadIdx.x;               // 0..127
    const float4* p = (const float4*)(W + row * HK + t * 8);
    float4 a = p[0], b = p[1];
    __half2 h0 = __floats2half2_rn(a.x, a.y), h1 = __floats2half2_rn(a.z, a.w);
    __half2 h2 = __floats2half2_rn(b.x, b.y), h3 = __floats2half2_rn(b.z, b.w);
    uint4 o;
    o.x = *(uint32_t*)&h0; o.y = *(uint32_t*)&h1;
    o.z = *(uint32_t*)&h2; o.w = *(uint32_t*)&h3;
    *(uint4*)(Wh + row * QKVN + coff + t * 8) = o;
}

// ---------------------------------------------------------------------------
// Embedding: x = emb[token] + pos ; also writes fp16
// ---------------------------------------------------------------------------
__global__ void embed_kernel(const int* __restrict__ tokens,
                             const float* __restrict__ emb,
                             const float* __restrict__ pos,
                             float* __restrict__ x,
                             __half* __restrict__ xh)
{
    int row = blockIdx.x;
    int s = row & (SEQ - 1);
    int t = tokens[row];
    const float4* e = (const float4*)(emb + (long)t * DMODEL);
    const float4* p = (const float4*)(pos + (long)s * DMODEL);
    for (int d = threadIdx.x; d < DMODEL / 4; d += blockDim.x) {
        float4 a = e[d], b = p[d];
        a.x += b.x; a.y += b.y; a.z += b.z; a.w += b.w;
        long o = (long)row * DMODEL + d * 4;
        *(float4*)&x[o] = a;
        __half2 h01, h23;
        h01.x = __float2half_rn(a.x); h01.y = __float2half_rn(a.y);
        h23.x = __float2half_rn(a.z); h23.y = __float2half_rn(a.w);
        *(__half2*)&xh[o] = h01; *(__half2*)&xh[o + 2] = h23;
    }
}

// qkv bias concat
__global__ void bias_concat_kernel(const float* __restrict__ bq, const float* __restrict__ bk,
                                   const float* __restrict__ bv, float* __restrict__ out)
{
    int i = blockIdx.x * blockDim.x + threadIdx.x;
    if (i >= NLAYER * QKVN) return;
    int l = i / QKVN, c = i - l * QKVN;
    float v = (c < 1024) ? bq[l * 1024 + c]
            : (c < 2048) ? bk[l * 1024 + c - 1024]
                         : bv[l * 1024 + c - 2048];
    out[i] = v;
}

// ---------------------------------------------------------------------------
// HMMA GEMM: C[M,N] = A[M,K] @ B  (A fp16 [M,K]; B fp16 [K,N] natural)
// CTA 128x128, BK=64, 8 warps (2x4), warp tile 64x32, mma.sync m16n8k16.
// 3-stage cp.async pipeline; 2 CTAs/SM.
// ---------------------------------------------------------------------------
#define ASTRIDE 144                 // A smem row stride bytes (64 halves + pad)
#define ATILE_B 18432               // [128][72] halves
#define BSTRIDE 272                 // B smem row stride bytes (128 halves + pad)
#define BTILE_B 17408               // [64][136] halves
#define STAGE_B (ATILE_B + BTILE_B)       // 35840
#define GEMM_SMEM (3 * STAGE_B)           // 107520

template<bool RELU, bool RESID, bool WF32, bool WH16>
__global__ __launch_bounds__(256, 2)
void hmma_gemm(const __half* __restrict__ A, const __half* __restrict__ B,
               const float* __restrict__ bias, const float* __restrict__ resid,
               float* __restrict__ Cf, __half* __restrict__ Ch,
               int N, int K)
{
    extern __shared__ char smem[];
    uint32_t sbase = smem_u32(smem);

    int tid = threadIdx.x;
    int lane = tid & 31;
    int wid = tid >> 5;
    int wm = wid & 1;
    int wn = wid >> 1;
    int row0 = blockIdx.x * 128;
    int ncol0 = blockIdx.y * 128;
    int nk = K >> 6;

    float c[4][4][4];
#pragma unroll
    for (int i = 0; i < 4; i++)
#pragma unroll
        for (int j = 0; j < 4; j++)
#pragma unroll
            for (int k = 0; k < 4; k++) c[i][j][k] = 0.f;

    auto load_stage = [&](int chunk, int buf) {
        uint32_t sb = sbase + buf * STAGE_B;
        int kc = chunk << 6;
#pragma unroll 4
        for (int i = tid; i < 1024; i += 256) {
            int r = i >> 3, sg = i & 7;
            cp_async16(sb + (uint32_t)(r * ASTRIDE + sg * 16),
                       A + (long)(row0 + r) * K + kc + sg * 8);
        }
#pragma unroll 4
        for (int i = tid; i < 1024; i += 256) {
            int r = i >> 4, cc = i & 15;
            cp_async16(sb + ATILE_B + (uint32_t)(r * BSTRIDE + cc * 16),
                       B + (long)(kc + r) * N + ncol0 + cc * 8);
        }
        cp_commit();
    };

    load_stage(0, 0);
    load_stage(1, 1);

    int arow = (lane & 7) + ((lane >> 3) & 1) * 8;
    int akk = ((lane >> 4) & 1) * 8;
    int bt = lane >> 3, br = lane & 7;
    int brow_off = (bt & 1) * 8 + br;
    int bcol_off = (bt >> 1) * 8;

    int buf = 0;
    for (int ch = 0; ch < nk; ch++) {
        if (ch + 1 < nk) cp_wait<1>(); else cp_wait<0>();
        __syncthreads();
        if (ch + 2 < nk) {
            int nb = buf + 2; if (nb >= 3) nb -= 3;
            load_stage(ch + 2, nb);
        }

        uint32_t sb = sbase + buf * STAGE_B;
#pragma unroll
        for (int ks = 0; ks < 4; ks++) {
            int k0 = ks * 16;
            uint32_t a_r[4][4], b_r[4][2];
#pragma unroll
            for (int mi = 0; mi < 4; mi++) {
                uint32_t ad = sb + (uint32_t)((wm * 64 + mi * 16 + arow) * ASTRIDE
                                              + (k0 + akk) * 2);
                ldsm_x4(a_r[mi], ad);
            }
#pragma unroll
            for (int p = 0; p < 2; p++) {
                uint32_t bd = sb + ATILE_B
                            + (uint32_t)((k0 + brow_off) * BSTRIDE
                                         + (wn * 32 + p * 16 + bcol_off) * 2);
                uint32_t r[4];
                ldsm_x4_trans(r, bd);
                b_r[2 * p][0] = r[0]; b_r[2 * p][1] = r[1];
                b_r[2 * p + 1][0] = r[2]; b_r[2 * p + 1][1] = r[3];
            }
#pragma unroll
            for (int mi = 0; mi < 4; mi++)
#pragma unroll
                for (int ni = 0; ni < 4; ni++)
                    mma_f16(c[mi][ni], a_r[mi], b_r[ni]);
        }
        if (++buf == 3) buf = 0;
    }

    int rbase = row0 + wm * 64 + (lane >> 2);
    int cbase = ncol0 + wn * 32 + (lane & 3) * 2;
#pragma unroll
    for (int mi = 0; mi < 4; mi++) {
#pragma unroll
        for (int ni = 0; ni < 4; ni++) {
            int gc = cbase + ni * 8;
            float b0 = __ldg(&bias[gc]), b1 = __ldg(&bias[gc + 1]);
#pragma unroll
            for (int half_ = 0; half_ < 2; half_++) {
                long gr = rbase + mi * 16 + half_ * 8;
                float v0 = c[mi][ni][half_ * 2 + 0] + b0;
                float v1 = c[mi][ni][half_ * 2 + 1] + b1;
                if (RELU) { v0 = fmaxf(v0, 0.f); v1 = fmaxf(v1, 0.f); }
                if (RESID) {
                    float2 rr = *(const float2*)&resid[gr * N + gc];
                    v0 += rr.x; v1 += rr.y;
                }
                if (WF32) {
                    float2 o; o.x = v0; o.y = v1;
                    *(float2*)&Cf[gr * N + gc] = o;
                }
                if (WH16) {
                    __half2 hh;
                    hh.x = __float2half_rn(v0); hh.y = __float2half_rn(v1);
                    *(__half2*)&Ch[gr * N + gc] = hh;
                }
            }
        }
    }
}

// ---------------------------------------------------------------------------
// HMMA flash attention. CTA = 128 q-rows x one head. 8 warps x 16 rows.
// (unchanged from round 11 — protect the win)
// ---------------------------------------------------------------------------
#define FSTR 144   // smem row stride bytes (64 halves + 8 pad)
#define FQ_B (128 * FSTR)          // 18432
#define FK_B (64 * FSTR)           // 9216
#define FLASH_SMEM2 (FQ_B + 2 * FK_B)  // 36864

__global__ __launch_bounds__(256, 2)
void flash_attn_hmma(const __half* __restrict__ QKV, __half* __restrict__ Ao)
{
    extern __shared__ char sm8[];
    uint32_t sq = smem_u32(sm8);
    uint32_t sk = sq + FQ_B;
    uint32_t sv = sk + FK_B;

    int qt = gridDim.x - 1 - blockIdx.x;
    int bh = blockIdx.y;
    int b = bh >> 4, h = bh & 15;
    int tid = threadIdx.x, lane = tid & 31, wid = tid >> 5;

    const __half* Qg = QKV + (long)b * SEQ * QKVN + h * HDIM;
    const __half* Kg = Qg + 1024;
    const __half* Vg = Qg + 2048;

    for (int i = tid; i < 1024; i += 256) {
        int r = i >> 3, sg = i & 7;
        cp_async16(sq + (uint32_t)(r * FSTR + sg * 16),
                   Qg + (long)(qt * 128 + r) * QKVN + sg * 8);
    }
    cp_commit();

    int arow = (lane & 7) + ((lane >> 3) & 1) * 8;
    int akk = ((lane >> 4) & 1) * 8;
    int bt = lane >> 3, br = lane & 7;
    int brow_off = (bt & 1) * 8 + br;
    int bcol_off = (bt >> 1) * 8;

    cp_wait<0>();
    __syncthreads();

    uint32_t a_q[4][4];
#pragma unroll
    for (int ks = 0; ks < 4; ks++)
        ldsm_x4(a_q[ks], sq + (uint32_t)((wid * 16 + arow) * FSTR + (ks * 16 + akk) * 2));

    float o[8][4];
#pragma unroll
    for (int i = 0; i < 8; i++)
#pragma unroll
        for (int j = 0; j < 4; j++) o[i][j] = 0.f;
    float m_[2] = {-1e30f, -1e30f}, l_[2] = {0.f, 0.f};

    int rloc = wid * 16 + (lane >> 2);
    int r0g = qt * 128 + rloc;
    int njt = 2 * qt + 2;

    for (int jt = 0; jt < njt; jt++) {
        __syncthreads();
        for (int i = tid; i < 512; i += 256) {
            int r = i >> 3, sg = i & 7;
            long g = (long)(jt * 64 + r) * QKVN + sg * 8;
            cp_async16(sk + (uint32_t)(r * FSTR + sg * 16), Kg + g);
            cp_async16(sv + (uint32_t)(r * FSTR + sg * 16), Vg + g);
        }
        cp_commit();
        cp_wait<0>();
        __syncthreads();

        float cs[8][4];
#pragma unroll
        for (int i = 0; i < 8; i++)
#pragma unroll
            for (int j = 0; j < 4; j++) cs[i][j] = 0.f;

#pragma unroll
        for (int ks = 0; ks < 4; ks++) {
            uint32_t b_r[8][2];
#pragma unroll
            for (int p = 0; p < 4; p++) {
                uint32_t r[4];
                ldsm_x4(r, sk + (uint32_t)((p * 16 + arow) * FSTR + (ks * 16 + akk) * 2));
                b_r[2 * p][0] = r[0]; b_r[2 * p + 1][0] = r[1];
                b_r[2 * p][1] = r[2]; b_r[2 * p + 1][1] = r[3];
            }
#pragma unroll
            for (int ni = 0; ni < 8; ni++)
                mma_f16(cs[ni], a_q[ks], b_r[ni]);
        }

        bool need_mask = (jt * 64 + 63) > (qt * 128 + wid * 16);
        if (need_mask) {
#pragma unroll
            for (int ni = 0; ni < 8; ni++) {
                int k0c = jt * 64 + ni * 8 + (lane & 3) * 2;
#pragma unroll
                for (int hf = 0; hf < 2; hf++) {
                    int qrow = r0g + hf * 8;
                    float v0 = cs[ni][hf * 2 + 0] * 0.125f;
                    float v1 = cs[ni][hf * 2 + 1] * 0.125f;
                    cs[ni][hf * 2 + 0] = (k0c > qrow) ? -1e30f : v0;
                    cs[ni][hf * 2 + 1] = (k0c + 1 > qrow) ? -1e30f : v1;
                }
            }
        } else {
#pragma unroll
            for (int ni = 0; ni < 8; ni++)
#pragma unroll
                for (int j = 0; j < 4; j++) cs[ni][j] *= 0.125f;
        }

#pragma unroll
        for (int hf = 0; hf < 2; hf++) {
            float mx = m_[hf];
#pragma unroll
            for (int ni = 0; ni < 8; ni++)
                mx = fmaxf(mx, fmaxf(cs[ni][hf * 2], cs[ni][hf * 2 + 1]));
            mx = fmaxf(mx, __shfl_xor_sync(0xffffffffu, mx, 1));
            mx = fmaxf(mx, __shfl_xor_sync(0xffffffffu, mx, 2));
            float corr = __expf(m_[hf] - mx);
            float rsum = 0.f;
#pragma unroll
            for (int ni = 0; ni < 8; ni++) {
                float p0 = __expf(cs[ni][hf * 2 + 0] - mx);
                float p1 = __expf(cs[ni][hf * 2 + 1] - mx);
                cs[ni][hf * 2 + 0] = p0;
                cs[ni][hf * 2 + 1] = p1;
                rsum += p0 + p1;
            }
            rsum += __shfl_xor_sync(0xffffffffu, rsum, 1);
            rsum += __shfl_xor_sync(0xffffffffu, rsum, 2);
            l_[hf] = l_[hf] * corr + rsum;
            m_[hf] = mx;
#pragma unroll
            for (int ni = 0; ni < 8; ni++) {
                o[ni][hf * 2 + 0] *= corr;
                o[ni][hf * 2 + 1] *= corr;
            }
        }

#pragma unroll
        for (int ks2 = 0; ks2 < 4; ks2++) {
            uint32_t a_p[4];
            {
                __half2 t0 = __floats2half2_rn(cs[2 * ks2][0], cs[2 * ks2][1]);
                __half2 t1 = __floats2half2_rn(cs[2 * ks2][2], cs[2 * ks2][3]);
                __half2 t2 = __floats2half2_rn(cs[2 * ks2 + 1][0], cs[2 * ks2 + 1][1]);
                __half2 t3 = __floats2half2_rn(cs[2 * ks2 + 1][2], cs[2 * ks2 + 1][3]);
                a_p[0] = *(uint32_t*)&t0; a_p[1] = *(uint32_t*)&t1;
                a_p[2] = *(uint32_t*)&t2; a_p[3] = *(uint32_t*)&t3;
            }
            uint32_t b_v[8][2];
#pragma unroll
            for (int p = 0; p < 4; p++) {
                uint32_t r[4];
                ldsm_x4_trans(r, sv + (uint32_t)((ks2 * 16 + brow_off) * FSTR
                                                 + (p * 16 + bcol_off) * 2));
                b_v[2 * p][0] = r[0]; b_v[2 * p][1] = r[1];
                b_v[2 * p + 1][0] = r[2]; b_v[2 * p + 1][1] = r[3];
            }
#pragma unroll
            for (int ni = 0; ni < 8; ni++)
                mma_f16(o[ni], a_p, b_v[ni]);
        }
    }

#pragma unroll
    for (int hf = 0; hf < 2; hf++) {
        float inv = 1.0f / l_[hf];
        long row = (long)(b * SEQ + r0g + hf * 8);
#pragma unroll
        for (int ni = 0; ni < 8; ni++) {
            __half2 hv = __floats2half2_rn(o[ni][hf * 2 + 0] * inv,
                                           o[ni][hf * 2 + 1] * inv);
            *(__half2*)&Ao[row * HK + h * HDIM + ni * 8 + (lane & 3) * 2] = hv;
        }
    }
}

// ---------------------------------------------------------------------------
// Launch
// ---------------------------------------------------------------------------
extern "C" void kernel_launch(void* const* d_in, const int* in_sizes, int n_in,
                              void* d_out, int out_size)
{
    const int*   tokens = (const int*)  d_in[0];
    const float* emb    = (const float*)d_in[1];
    const float* pos    = (const float*)d_in[2];
    const float* Wq     = (const float*)d_in[3];
    const float* bq     = (const float*)d_in[4];
    const float* Wk     = (const float*)d_in[5];
    const float* bk     = (const float*)d_in[6];
    const float* Wv     = (const float*)d_in[7];
    const float* bv     = (const float*)d_in[8];
    const float* Wo     = (const float*)d_in[9];
    const float* bo     = (const float*)d_in[10];
    const float* W1     = (const float*)d_in[11];
    const float* b1     = (const float*)d_in[12];
    const float* W2     = (const float*)d_in[13];
    const float* b2     = (const float*)d_in[14];
    const float* Wf     = (const float*)d_in[15];
    const float* bf     = (const float*)d_in[16];
    float* out = (float*)d_out;

    float *x, *qkvb;
    __half *qkvh, *xh, *ah, *fh;
    __half *wqkv, *wo, *w1, *w2, *wf;
    cudaGetSymbolAddress((void**)&x, g_x);
    cudaGetSymbolAddress((void**)&qkvb, g_qkvb);
    cudaGetSymbolAddress((void**)&qkvh, g_qkvh);
    cudaGetSymbolAddress((void**)&xh, g_xh);
    cudaGetSymbolAddress((void**)&ah, g_ah);
    cudaGetSymbolAddress((void**)&fh, g_fh);
    cudaGetSymbolAddress((void**)&wqkv, g_wqkv);
    cudaGetSymbolAddress((void**)&wo, g_wo);
    cudaGetSymbolAddress((void**)&w1, g_w1);
    cudaGetSymbolAddress((void**)&w2, g_w2);
    cudaGetSymbolAddress((void**)&wf, g_wf);

    static bool attr_set = false;
    if (!attr_set) {
        cudaFuncSetAttribute(flash_attn_hmma,
                             cudaFuncAttributeMaxDynamicSharedMemorySize, FLASH_SMEM2);
        cudaFuncSetAttribute(hmma_gemm<false, false, true, false>,
                             cudaFuncAttributeMaxDynamicSharedMemorySize, GEMM_SMEM);
        cudaFuncSetAttribute(hmma_gemm<false, false, false, true>,
                             cudaFuncAttributeMaxDynamicSharedMemorySize, GEMM_SMEM);
        cudaFuncSetAttribute(hmma_gemm<false, true, true, true>,
                             cudaFuncAttributeMaxDynamicSharedMemorySize, GEMM_SMEM);
        cudaFuncSetAttribute(hmma_gemm<true, false, false, true>,
                             cudaFuncAttributeMaxDynamicSharedMemorySize, GEMM_SMEM);
        attr_set = true;
    }

    // ---- weight convert: 8 launches total (all layers fused per tensor) ----
    // qkv packed: grid = NLAYER*DMODEL rows; out row stride QKVN holds across layers
    wconv_qkv<<<NLAYER * DMODEL, 128>>>(Wq, wqkv, 0);
    wconv_qkv<<<NLAYER * DMODEL, 128>>>(Wk, wqkv, 1024);
    wconv_qkv<<<NLAYER * DMODEL, 128>>>(Wv, wqkv, 2048);
    // flat tensors
    {
        long n8;
        n8 = (long)NLAYER * HK * DMODEL / 8;            // 512K
        wconv_flat<<<(unsigned)((n8 + 255) / 256), 256>>>(Wo, wo, n8);
        n8 = (long)NLAYER * DMODEL * FFDIM / 8;         // 2M
        wconv_flat<<<(unsigned)((n8 + 255) / 256), 256>>>(W1, w1, n8);
        wconv_flat<<<(unsigned)((n8 + 255) / 256), 256>>>(W2, w2, n8);
        n8 = (long)DMODEL * VOCAB / 8;                  // 4.096M
        wconv_flat<<<(unsigned)((n8 + 255) / 256), 256>>>(Wf, wf, n8);
    }
    bias_concat_kernel<<<(NLAYER * QKVN + 255) / 256, 256>>>(bq, bk, bv, qkvb);

    // ---- forward ----
    embed_kernel<<<MTOK, 256>>>(tokens, emb, pos, x, xh);

    dim3 gQKV(MTOK / 128, QKVN / 128);
    dim3 gProj(MTOK / 128, DMODEL / 128);
    dim3 gFF1(MTOK / 128, FFDIM / 128);
    dim3 gLogits(MTOK / 128, VOCAB / 128);
    dim3 gAttn(SEQ / 128, BATCH * NHEAD);   // 16 x 32

    for (int l = 0; l < NLAYER; l++) {
        // qkv = x @ Wqkv + b  (fp16 out)
        hmma_gemm<false, false, false, true><<<gQKV, 256, GEMM_SMEM>>>(
            xh, wqkv + (long)l * DMODEL * QKVN, qkvb + (long)l * QKVN, nullptr,
            nullptr, qkvh, QKVN, DMODEL);

        flash_attn_hmma<<<gAttn, 256, FLASH_SMEM2>>>(qkvh, ah);

        // x = x + a @ Wo + bo  (fp32 + fp16 out)
        hmma_gemm<false, true, true, true><<<gProj, 256, GEMM_SMEM>>>(
            ah, wo + (long)l * HK * DMODEL,
            bo + (long)l * DMODEL, x, x, xh, DMODEL, HK);

        // f = relu(x @ W1 + b1)  (fp16 only)
        hmma_gemm<true, false, false, true><<<gFF1, 256, GEMM_SMEM>>>(
            xh, w1 + (long)l * DMODEL * FFDIM,
            b1 + (long)l * FFDIM, nullptr, nullptr, fh, FFDIM, DMODEL);

        // x = x + f @ W2 + b2
        hmma_gemm<false, true, true, true><<<gProj, 256, GEMM_SMEM>>>(
            fh, w2 + (long)l * FFDIM * DMODEL,
            b2 + (long)l * DMODEL, x, x, xh, DMODEL, FFDIM);
    }

    // logits = x @ Wf + bf
    hmma_gemm<false, false, true, false><<<gLogits, 256, GEMM_SMEM>>>(
        xh, wf, bf, nullptr, out, nullptr, VOCAB, DMODEL);
}